// round 1
// baseline (speedup 1.0000x reference)
#include <cuda_runtime.h>
#include <cuda_bf16.h>
#include <cstdint>

// ---------------------------------------------------------------------------
// Problem constants (fixed shapes)
// ---------------------------------------------------------------------------
#define T_TOK   2048      // B*S
#define D_DIM   2880
#define N_HEADS 64
#define K_HEADS 8
#define H_DIM   64
#define S_LEN   1024
#define B_BATCH 2
#define WIN     128
#define NH      4096      // N_HEADS*H_DIM
#define KVH     512       // K_HEADS*H_DIM
#define QKV_COLS 5120     // 4096 + 512 + 512

// ---------------------------------------------------------------------------
// Scratch (static device arrays; no allocation allowed)
// ---------------------------------------------------------------------------
__device__ __nv_bfloat16 g_xhi[T_TOK * D_DIM];
__device__ __nv_bfloat16 g_xlo[T_TOK * D_DIM];
__device__ __nv_bfloat16 g_wqhi[D_DIM * NH];
__device__ __nv_bfloat16 g_wqlo[D_DIM * NH];
__device__ __nv_bfloat16 g_wkhi[D_DIM * KVH];
__device__ __nv_bfloat16 g_wklo[D_DIM * KVH];
__device__ __nv_bfloat16 g_wvhi[D_DIM * KVH];
__device__ __nv_bfloat16 g_wvlo[D_DIM * KVH];
__device__ __nv_bfloat16 g_wohi[NH * D_DIM];
__device__ __nv_bfloat16 g_wolo[NH * D_DIM];
__device__ float         g_qkv[T_TOK * QKV_COLS];
__device__ float         g_ctx[T_TOK * NH];
__device__ __nv_bfloat16 g_chi[T_TOK * NH];
__device__ __nv_bfloat16 g_clo[T_TOK * NH];

// ---------------------------------------------------------------------------
// Split fp32 -> (bf16 hi, bf16 lo)
// ---------------------------------------------------------------------------
__global__ void split_kernel(const float* __restrict__ in,
                             __nv_bfloat16* __restrict__ hi,
                             __nv_bfloat16* __restrict__ lo, int n) {
    int i = blockIdx.x * blockDim.x + threadIdx.x;
    int stride = gridDim.x * blockDim.x;
    for (; i < n; i += stride) {
        float x = in[i];
        __nv_bfloat16 h = __float2bfloat16(x);
        hi[i] = h;
        lo[i] = __float2bfloat16(x - __bfloat162float(h));
    }
}

// ---------------------------------------------------------------------------
// GEMM: C[M,Nd] = A[M,Kd] @ B[Kd,Nd] + bias, A/B given as bf16 hi/lo planes.
// 3-term split: C += Ahi*Bhi + Ahi*Blo + Alo*Bhi  (near-fp32 accuracy).
// Block tile 128x128, K-chunk 32, 8 warps (64x32 warp tiles), mma.m16n8k16.
// ---------------------------------------------------------------------------
__device__ __forceinline__ void mma16816(float* c, const uint32_t* a, const uint32_t* b) {
    asm volatile(
        "mma.sync.aligned.m16n8k16.row.col.f32.bf16.bf16.f32 "
        "{%0,%1,%2,%3},{%4,%5,%6,%7},{%8,%9},{%0,%1,%2,%3};\n"
        : "+f"(c[0]), "+f"(c[1]), "+f"(c[2]), "+f"(c[3])
        : "r"(a[0]), "r"(a[1]), "r"(a[2]), "r"(a[3]), "r"(b[0]), "r"(b[1]));
}

#define A_PITCH 40
#define B_PITCH 136

__global__ __launch_bounds__(256) void gemm_bf16split(
    const __nv_bfloat16* __restrict__ Ahi, const __nv_bfloat16* __restrict__ Alo,
    const __nv_bfloat16* __restrict__ Bhi, const __nv_bfloat16* __restrict__ Blo,
    const float* __restrict__ bias, float* __restrict__ C,
    int M, int Kd, int Nd, int ldc)
{
    __shared__ __align__(16) __nv_bfloat16 sAhi[128 * A_PITCH];
    __shared__ __align__(16) __nv_bfloat16 sAlo[128 * A_PITCH];
    __shared__ __align__(16) __nv_bfloat16 sBhi[32 * B_PITCH];
    __shared__ __align__(16) __nv_bfloat16 sBlo[32 * B_PITCH];

    const int tid  = threadIdx.x;
    const int lane = tid & 31;
    const int warp = tid >> 5;
    const int wm = warp >> 2;       // 0..1
    const int wn = warp & 3;        // 0..3
    const int g  = lane >> 2;       // group id 0..7
    const int tg = lane & 3;        // thread-in-group 0..3
    const int m0 = blockIdx.y * 128;
    const int n0 = blockIdx.x * 128;

    float c[4][4][4];
#pragma unroll
    for (int mi = 0; mi < 4; mi++)
#pragma unroll
        for (int ni = 0; ni < 4; ni++)
#pragma unroll
            for (int r = 0; r < 4; r++) c[mi][ni][r] = 0.0f;

    for (int kt = 0; kt < Kd; kt += 32) {
        // --- load A tile (128 rows x 32 k) as bf16x2 pairs ---
#pragma unroll
        for (int i = 0; i < 8; i++) {
            int pid = tid + i * 256;            // 0..2047
            int r = pid >> 4;                   // 0..127
            int kp = pid & 15;                  // pair index 0..15
            size_t ga = (size_t)(m0 + r) * Kd + kt + kp * 2;
            *(uint32_t*)(sAhi + r * A_PITCH + kp * 2) = *(const uint32_t*)(Ahi + ga);
            *(uint32_t*)(sAlo + r * A_PITCH + kp * 2) = *(const uint32_t*)(Alo + ga);
        }
        // --- load B tile (32 k x 128 n) as bf16x2 pairs, zero OOB cols ---
#pragma unroll
        for (int i = 0; i < 8; i++) {
            int pid = tid + i * 256;            // 0..2047
            int kk = pid >> 6;                  // 0..31
            int jn = pid & 63;                  // pair index 0..63
            int col = n0 + jn * 2;
            uint32_t vhi = 0u, vlo = 0u;
            if (col < Nd) {
                size_t gb = (size_t)(kt + kk) * Nd + col;
                vhi = *(const uint32_t*)(Bhi + gb);
                vlo = *(const uint32_t*)(Blo + gb);
            }
            *(uint32_t*)(sBhi + kk * B_PITCH + jn * 2) = vhi;
            *(uint32_t*)(sBlo + kk * B_PITCH + jn * 2) = vlo;
        }
        __syncthreads();

#pragma unroll
        for (int ks = 0; ks < 2; ks++) {
            const int kb = ks * 16 + tg * 2;
            uint32_t ahi[4][4], alo[4][4], bhi[4][2], blo[4][2];
#pragma unroll
            for (int mi = 0; mi < 4; mi++) {
                int r0 = wm * 64 + mi * 16 + g;
                ahi[mi][0] = *(const uint32_t*)(sAhi + r0 * A_PITCH + kb);
                ahi[mi][1] = *(const uint32_t*)(sAhi + (r0 + 8) * A_PITCH + kb);
                ahi[mi][2] = *(const uint32_t*)(sAhi + r0 * A_PITCH + kb + 8);
                ahi[mi][3] = *(const uint32_t*)(sAhi + (r0 + 8) * A_PITCH + kb + 8);
                alo[mi][0] = *(const uint32_t*)(sAlo + r0 * A_PITCH + kb);
                alo[mi][1] = *(const uint32_t*)(sAlo + (r0 + 8) * A_PITCH + kb);
                alo[mi][2] = *(const uint32_t*)(sAlo + r0 * A_PITCH + kb + 8);
                alo[mi][3] = *(const uint32_t*)(sAlo + (r0 + 8) * A_PITCH + kb + 8);
            }
#pragma unroll
            for (int ni = 0; ni < 4; ni++) {
                int col = wn * 32 + ni * 8 + g;
                const uint16_t* ph = (const uint16_t*)sBhi;
                const uint16_t* pl = (const uint16_t*)sBlo;
                bhi[ni][0] = (uint32_t)ph[kb * B_PITCH + col] |
                             ((uint32_t)ph[(kb + 1) * B_PITCH + col] << 16);
                bhi[ni][1] = (uint32_t)ph[(kb + 8) * B_PITCH + col] |
                             ((uint32_t)ph[(kb + 9) * B_PITCH + col] << 16);
                blo[ni][0] = (uint32_t)pl[kb * B_PITCH + col] |
                             ((uint32_t)pl[(kb + 1) * B_PITCH + col] << 16);
                blo[ni][1] = (uint32_t)pl[(kb + 8) * B_PITCH + col] |
                             ((uint32_t)pl[(kb + 9) * B_PITCH + col] << 16);
            }
#pragma unroll
            for (int mi = 0; mi < 4; mi++)
#pragma unroll
                for (int ni = 0; ni < 4; ni++) {
                    mma16816(c[mi][ni], ahi[mi], bhi[ni]);
                    mma16816(c[mi][ni], ahi[mi], blo[ni]);
                    mma16816(c[mi][ni], alo[mi], bhi[ni]);
                }
        }
        __syncthreads();
    }

    // --- epilogue: bias add + store ---
#pragma unroll
    for (int mi = 0; mi < 4; mi++) {
        int row = m0 + wm * 64 + mi * 16 + g;
#pragma unroll
        for (int ni = 0; ni < 4; ni++) {
            int col = n0 + wn * 32 + ni * 8 + tg * 2;
            if (col < Nd) {
                float b0 = bias[col], b1 = bias[col + 1];
                float* p0 = C + (size_t)row * ldc + col;
                float* p1 = C + (size_t)(row + 8) * ldc + col;
                p0[0] = c[mi][ni][0] + b0;
                p0[1] = c[mi][ni][1] + b1;
                p1[0] = c[mi][ni][2] + b0;
                p1[1] = c[mi][ni][3] + b1;
            }
        }
    }
}

// ---------------------------------------------------------------------------
// RoPE (YaRN-style NTK interpolation), in place on q (heads 0..63) and
// k (heads 64..71) of the fused qkv buffer. Cols 0..4607 are contiguous.
// ---------------------------------------------------------------------------
__global__ void rope_kernel(float* __restrict__ qkv, const int* __restrict__ positions) {
    __shared__ float cs[32], sn[32];
    const int t = blockIdx.x;
    const int pos = positions[t] % S_LEN;
    if (threadIdx.x < 32) {
        int i = threadIdx.x;
        float freq   = powf(150000.0f, (float)i / 32.0f);
        float interp = 1.0f / (32.0f * freq);
        float extrap = 1.0f / freq;
        float lnT    = logf(150000.0f);
        float low    = 32.0f * logf(4096.0f / (32.0f * 6.2831853071795864f)) / lnT;
        float high   = 32.0f * logf(4096.0f / 6.2831853071795864f) / lnT;
        float ramp   = fminf(fmaxf(((float)i - low) / (high - low), 0.0f), 1.0f);
        float inv    = interp * ramp + extrap * (1.0f - ramp);
        float conc   = 0.1f * logf(32.0f) + 1.0f;
        float tt     = (float)pos * inv;
        cs[i] = cosf(tt) * conc;
        sn[i] = sinf(tt) * conc;
    }
    __syncthreads();
    for (int idx = threadIdx.x; idx < 72 * 32; idx += blockDim.x) {
        int head = idx >> 5;
        int i = idx & 31;
        float* base = qkv + (size_t)t * QKV_COLS + head * 64;
        float x1 = base[i], x2 = base[i + 32];
        base[i]      = x1 * cs[i] - x2 * sn[i];
        base[i + 32] = x2 * cs[i] + x1 * sn[i];
    }
}

// ---------------------------------------------------------------------------
// Sliding-window attention with sinks. One block per (query, kv-head, batch),
// 8 GQA heads share the K/V tile staged in shared memory.
// ---------------------------------------------------------------------------
__global__ void attn_kernel(const float* __restrict__ qkv,
                            const float* __restrict__ sinks,
                            float* __restrict__ ctx) {
    extern __shared__ float sm[];
    float* ks  = sm;                 // 128*65
    float* vs  = ks + 128 * 65;      // 128*65
    float* qs  = vs + 128 * 65;      // 512
    float* sc  = qs + 512;           // 128
    float* red = sc + 128;           // 8

    const int qi  = blockIdx.x;
    const int kh  = blockIdx.y;
    const int b   = blockIdx.z;
    const int tid = threadIdx.x;
    const int t   = b * S_LEN + qi;
    const int kstart = (qi >= WIN - 1) ? qi - (WIN - 1) : 0;
    const int cnt = qi - kstart + 1;

    // load 8 query heads (contiguous 512 floats at col kh*512)
    for (int i = tid; i < 512; i += 128)
        qs[i] = qkv[(size_t)t * QKV_COLS + kh * 512 + i];
    // load K/V window
    for (int i = tid; i < cnt * 64; i += 128) {
        int r = i >> 6, d = i & 63;
        size_t rowbase = (size_t)(b * S_LEN + kstart + r) * QKV_COLS;
        ks[r * 65 + d] = qkv[rowbase + 4096 + kh * 64 + d];
        vs[r * 65 + d] = qkv[rowbase + 4608 + kh * 64 + d];
    }
    __syncthreads();

    for (int h8 = 0; h8 < 8; h8++) {
        const int n = kh * 8 + h8;
        float s = -1e30f;
        if (tid < cnt) {
            float acc = 0.0f;
            const float* kr = ks + tid * 65;
            const float* qr = qs + h8 * 64;
#pragma unroll
            for (int d = 0; d < 64; d++) acc = fmaf(qr[d], kr[d], acc);
            s = acc * 0.125f;   // 1/sqrt(64)
        }
        // block max
        float m = s;
#pragma unroll
        for (int o = 16; o; o >>= 1) m = fmaxf(m, __shfl_xor_sync(0xffffffffu, m, o));
        if ((tid & 31) == 0) red[tid >> 5] = m;
        __syncthreads();
        m = fmaxf(fmaxf(red[0], red[1]), fmaxf(red[2], red[3]));
        const float sink = sinks[n];
        m = fmaxf(m, sink);

        float p = (tid < cnt) ? __expf(s - m) : 0.0f;
        sc[tid] = p;
        float ps = p;
#pragma unroll
        for (int o = 16; o; o >>= 1) ps += __shfl_xor_sync(0xffffffffu, ps, o);
        __syncthreads();
        if ((tid & 31) == 0) red[4 + (tid >> 5)] = ps;
        __syncthreads();
        const float denom = red[4] + red[5] + red[6] + red[7] + __expf(sink - m);

        if (tid < 64) {
            float acc = 0.0f;
            for (int j = 0; j < cnt; j++) acc = fmaf(sc[j], vs[j * 65 + tid], acc);
            ctx[(size_t)t * NH + n * 64 + tid] = acc / denom;
        }
        __syncthreads();
    }
}

// ---------------------------------------------------------------------------
// Launch
// ---------------------------------------------------------------------------
extern "C" void kernel_launch(void* const* d_in, const int* in_sizes, int n_in,
                              void* d_out, int out_size) {
    const float* x     = (const float*)d_in[0];
    const float* wq    = (const float*)d_in[1];
    const float* bq    = (const float*)d_in[2];
    const float* wk    = (const float*)d_in[3];
    const float* bk    = (const float*)d_in[4];
    const float* wv    = (const float*)d_in[5];
    const float* bv    = (const float*)d_in[6];
    const float* wo    = (const float*)d_in[7];
    const float* bo    = (const float*)d_in[8];
    const float* sinks = (const float*)d_in[9];
    const int* positions = (const int*)d_in[10];
    float* out = (float*)d_out;

    void *xhi, *xlo, *wqhi, *wqlo, *wkhi, *wklo, *wvhi, *wvlo, *wohi, *wolo;
    void *qkv, *ctx, *chi, *clo;
    cudaGetSymbolAddress(&xhi, g_xhi);   cudaGetSymbolAddress(&xlo, g_xlo);
    cudaGetSymbolAddress(&wqhi, g_wqhi); cudaGetSymbolAddress(&wqlo, g_wqlo);
    cudaGetSymbolAddress(&wkhi, g_wkhi); cudaGetSymbolAddress(&wklo, g_wklo);
    cudaGetSymbolAddress(&wvhi, g_wvhi); cudaGetSymbolAddress(&wvlo, g_wvlo);
    cudaGetSymbolAddress(&wohi, g_wohi); cudaGetSymbolAddress(&wolo, g_wolo);
    cudaGetSymbolAddress(&qkv, g_qkv);   cudaGetSymbolAddress(&ctx, g_ctx);
    cudaGetSymbolAddress(&chi, g_chi);   cudaGetSymbolAddress(&clo, g_clo);

    // 1. split inputs/weights into bf16 hi/lo planes
    split_kernel<<<4096, 256>>>(x,  (__nv_bfloat16*)xhi,  (__nv_bfloat16*)xlo,  T_TOK * D_DIM);
    split_kernel<<<4096, 256>>>(wq, (__nv_bfloat16*)wqhi, (__nv_bfloat16*)wqlo, D_DIM * NH);
    split_kernel<<<2048, 256>>>(wk, (__nv_bfloat16*)wkhi, (__nv_bfloat16*)wklo, D_DIM * KVH);
    split_kernel<<<2048, 256>>>(wv, (__nv_bfloat16*)wvhi, (__nv_bfloat16*)wvlo, D_DIM * KVH);
    split_kernel<<<4096, 256>>>(wo, (__nv_bfloat16*)wohi, (__nv_bfloat16*)wolo, NH * D_DIM);

    // 2. QKV projections into fused buffer (q | k | v columns)
    float* qkvp = (float*)qkv;
    gemm_bf16split<<<dim3(32, 16), 256>>>(
        (__nv_bfloat16*)xhi, (__nv_bfloat16*)xlo,
        (__nv_bfloat16*)wqhi, (__nv_bfloat16*)wqlo,
        bq, qkvp, T_TOK, D_DIM, NH, QKV_COLS);
    gemm_bf16split<<<dim3(4, 16), 256>>>(
        (__nv_bfloat16*)xhi, (__nv_bfloat16*)xlo,
        (__nv_bfloat16*)wkhi, (__nv_bfloat16*)wklo,
        bk, qkvp + 4096, T_TOK, D_DIM, KVH, QKV_COLS);
    gemm_bf16split<<<dim3(4, 16), 256>>>(
        (__nv_bfloat16*)xhi, (__nv_bfloat16*)xlo,
        (__nv_bfloat16*)wvhi, (__nv_bfloat16*)wvlo,
        bv, qkvp + 4608, T_TOK, D_DIM, KVH, QKV_COLS);

    // 3. RoPE on q and k (in place)
    rope_kernel<<<T_TOK, 256>>>(qkvp, positions);

    // 4. attention
    const int attn_smem = (128 * 65 * 2 + 512 + 128 + 8) * (int)sizeof(float);
    cudaFuncSetAttribute(attn_kernel, cudaFuncAttributeMaxDynamicSharedMemorySize, attn_smem);
    attn_kernel<<<dim3(S_LEN, K_HEADS, B_BATCH), 128, attn_smem>>>(
        qkvp, sinks, (float*)ctx);

    // 5. split ctx, output projection
    split_kernel<<<4096, 256>>>((const float*)ctx, (__nv_bfloat16*)chi, (__nv_bfloat16*)clo, T_TOK * NH);
    gemm_bf16split<<<dim3(23, 16), 256>>>(
        (__nv_bfloat16*)chi, (__nv_bfloat16*)clo,
        (__nv_bfloat16*)wohi, (__nv_bfloat16*)wolo,
        bo, out, T_TOK, NH, D_DIM, D_DIM);
}

// round 3
// speedup vs baseline: 1.8414x; 1.8414x over previous
#include <cuda_runtime.h>
#include <cuda_fp16.h>
#include <cstdint>

// ---------------------------------------------------------------------------
// Problem constants
// ---------------------------------------------------------------------------
#define T_TOK   2048
#define D_DIM   2880
#define S_LEN   1024
#define B_BATCH 2
#define WIN     128
#define NH      4096
#define KVH     512
#define QKV_COLS 5120
#define OPAD    2944
#define NKC_QKV 90        // 2880/32 k-chunks
#define NKC_O   128       // 4096/32

// ---------------------------------------------------------------------------
// Scratch
// ---------------------------------------------------------------------------
__device__ __half g_xpk [(size_t)8  * NKC_QKV * 256 * 32];   // x packed fp16
__device__ __half g_wbh [(size_t)40 * NKC_QKV * 128 * 32];   // qkv weights hi
__device__ __half g_wbl [(size_t)40 * NKC_QKV * 128 * 32];   // qkv weights lo
__device__ __half g_wobh[(size_t)23 * NKC_O   * 128 * 32];   // wo hi
__device__ __half g_wobl[(size_t)23 * NKC_O   * 128 * 32];   // wo lo
__device__ __half g_cpk [(size_t)8  * NKC_O   * 256 * 32];   // ctx packed fp16
__device__ float  g_qkv [(size_t)T_TOK * QKV_COLS];
__device__ float  g_biasqkv[QKV_COLS];

// ---------------------------------------------------------------------------
// Packed-layout offsets.  Blobs: A-operand tiles 256 rows x 32 k (fp16),
// B-operand tiles 128 rows x 32 k.  Within a row (64B = 4 x 16B chunks) the
// chunk index is XOR-swizzled with ((row>>1)&3) so ldmatrix reads are
// bank-conflict free while cp.async.bulk copies stay linear.
// ---------------------------------------------------------------------------
__device__ __forceinline__ size_t offA(int t, int k, int nkc) {
    int r = t & 255, ck = (k >> 3) & 3, w = k & 7;
    return ((((size_t)(t >> 8)) * nkc + (k >> 5)) * 256 + r) * 32 +
           (((ck ^ ((r >> 1) & 3)) << 3) + w);
}
__device__ __forceinline__ size_t offB(int n, int k, int nkc) {
    int r = n & 127, ck = (k >> 3) & 3, w = k & 7;
    return ((((size_t)(n >> 7)) * nkc + (k >> 5)) * 128 + r) * 32 +
           (((ck ^ ((r >> 1) & 3)) << 3) + w);
}

// ---------------------------------------------------------------------------
// PTX helpers
// ---------------------------------------------------------------------------
__device__ __forceinline__ void mbar_init(uint32_t a, uint32_t cnt) {
    asm volatile("mbarrier.init.shared.b64 [%0], %1;" :: "r"(a), "r"(cnt) : "memory");
}
__device__ __forceinline__ void mbar_wait(uint32_t a, int ph) {
    uint32_t done = 0;
    while (!done) {
        asm volatile("{\n\t.reg .pred p;\n\t"
                     "mbarrier.try_wait.parity.acquire.cta.shared::cta.b64 p, [%1], %2, 0x989680;\n\t"
                     "selp.b32 %0,1,0,p;\n\t}"
                     : "=r"(done) : "r"(a), "r"((uint32_t)ph) : "memory");
    }
}
__device__ __forceinline__ void expect_tx(uint32_t a, uint32_t bytes) {
    asm volatile("mbarrier.arrive.expect_tx.shared::cta.b64 _, [%0], %1;"
                 :: "r"(a), "r"(bytes) : "memory");
}
__device__ __forceinline__ void bulk_g2s(uint32_t sdst, const void* gsrc,
                                         uint32_t bytes, uint32_t mbar) {
    asm volatile("cp.async.bulk.shared::cluster.global.mbarrier::complete_tx::bytes "
                 "[%0], [%1], %2, [%3];"
                 :: "r"(sdst), "l"(__cvta_generic_to_global(gsrc)), "r"(bytes), "r"(mbar)
                 : "memory");
}
__device__ __forceinline__ void ldmx4(uint32_t* d, uint32_t addr) {
    asm volatile("ldmatrix.sync.aligned.m8n8.x4.shared.b16 {%0,%1,%2,%3}, [%4];"
                 : "=r"(d[0]), "=r"(d[1]), "=r"(d[2]), "=r"(d[3]) : "r"(addr));
}
__device__ __forceinline__ void mma16816(float* c, const uint32_t* a, const uint32_t* b) {
    asm volatile(
        "mma.sync.aligned.m16n8k16.row.col.f32.f16.f16.f32 "
        "{%0,%1,%2,%3},{%4,%5,%6,%7},{%8,%9},{%0,%1,%2,%3};\n"
        : "+f"(c[0]), "+f"(c[1]), "+f"(c[2]), "+f"(c[3])
        : "r"(a[0]), "r"(a[1]), "r"(a[2]), "r"(a[3]), "r"(b[0]), "r"(b[1]));
}

// ---------------------------------------------------------------------------
// Prep: pack x (fp16, A layout)
// ---------------------------------------------------------------------------
__global__ void pack_x(const float* __restrict__ x, __half* __restrict__ o) {
    int k = blockIdx.x * 256 + threadIdx.x;
    int t = blockIdx.y;
    if (k < D_DIM)
        o[offA(t, k, NKC_QKV)] = __float2half_rn(x[(size_t)t * D_DIM + k]);
}

// Prep: transpose + split weights into packed hi/lo B layout.
// in: [R][C] fp32 (R = k-dim rows, C = real out-cols). out n = nbase + c, k = r.
__global__ void tsp(const float* __restrict__ in, __half* __restrict__ oh,
                    __half* __restrict__ ol, int R, int C, int nkc, int nbase) {
    __shared__ float tb[32][33];
    int c0 = blockIdx.x * 32, r0 = blockIdx.y * 32;
    int tx = threadIdx.x, ty = threadIdx.y;
#pragma unroll
    for (int i = 0; i < 4; i++) {
        int r = r0 + ty + i * 8, c = c0 + tx;
        tb[ty + i * 8][tx] = (c < C) ? in[(size_t)r * C + c] : 0.0f;
    }
    __syncthreads();
#pragma unroll
    for (int i = 0; i < 4; i++) {
        int n = nbase + c0 + ty + i * 8, k = r0 + tx;
        float v = tb[tx][ty + i * 8];
        __half h = __float2half_rn(v);
        __half l = __float2half_rn(v - __half2float(h));
        size_t o = offB(n, k, nkc);
        oh[o] = h;
        ol[o] = l;
    }
}

__global__ void concat_bias(const float* __restrict__ bq, const float* __restrict__ bk,
                            const float* __restrict__ bv, float* __restrict__ out) {
    int i = blockIdx.x * blockDim.x + threadIdx.x;
    if (i < QKV_COLS)
        out[i] = (i < NH) ? bq[i] : (i < NH + KVH ? bk[i - NH] : bv[i - NH - KVH]);
}

// ---------------------------------------------------------------------------
// GEMM: C[M,N] = A(fp16) @ (Bh+Bl)(fp16)^T + bias, fp32 accumulate.
// CTA tile 256x128, k-chunk 32, 512 threads (16 warps, 64x32 warp tiles),
// 3-stage cp.async.bulk pipeline with mbarriers, ldmatrix fragments.
// ---------------------------------------------------------------------------
#define STAGE_BYTES 32768
#define GEMM_SMEM   (128 + 3 * STAGE_BYTES)

__global__ __launch_bounds__(512, 1) void gemm_tc(
    const __half* __restrict__ Apk, const __half* __restrict__ Bhp,
    const __half* __restrict__ Blp, const float* __restrict__ bias,
    float* __restrict__ C, int nkc, int Nreal, int ldc)
{
    extern __shared__ __align__(128) uint8_t dsm[];
    const uint32_t base = (uint32_t)__cvta_generic_to_shared(dsm);
    const uint32_t mb = base;
    const uint32_t sdata = base + 128;

    const int tid = threadIdx.x, lane = tid & 31, warp = tid >> 5;
    const int wm = warp >> 2, wn = warp & 3;
    const int mt = blockIdx.y, nt = blockIdx.x;

    if (tid == 0) { mbar_init(mb, 1); mbar_init(mb + 8, 1); mbar_init(mb + 16, 1); }
    __syncthreads();

    const __half* Asrc  = Apk + (size_t)mt * nkc * 8192;
    const __half* Bhsrc = Bhp + (size_t)nt * nkc * 4096;
    const __half* Blsrc = Blp + (size_t)nt * nkc * 4096;

    float c[4][4][4];
#pragma unroll
    for (int mi = 0; mi < 4; mi++)
#pragma unroll
        for (int ni = 0; ni < 4; ni++)
#pragma unroll
            for (int r = 0; r < 4; r++) c[mi][ni][r] = 0.0f;

    if (tid == 0) {
#pragma unroll
        for (int s = 0; s < 2; s++) {
            uint32_t sb = sdata + s * STAGE_BYTES;
            expect_tx(mb + s * 8, 32768u);
            bulk_g2s(sb,         Asrc  + (size_t)s * 8192, 16384, mb + s * 8);
            bulk_g2s(sb + 16384, Bhsrc + (size_t)s * 4096,  8192, mb + s * 8);
            bulk_g2s(sb + 24576, Blsrc + (size_t)s * 4096,  8192, mb + s * 8);
        }
    }

    // lane-invariant fragment addressing pieces
    const int rA_l = lane & 15;            // A row-in-16 offset
    const int ckA_l = lane >> 4;           // A chunk bit
    const int rB_l = (lane & 7) + ((lane >> 4) << 3);
    const int ckB_l = (lane >> 3) & 1;

    for (int i = 0; i < nkc; i++) {
        const int s = i - (i / 3) * 3;
        const int ph = (i / 3) & 1;
        mbar_wait(mb + s * 8, ph);

        const uint32_t sA  = sdata + s * STAGE_BYTES;
        const uint32_t sBh = sA + 16384;
        const uint32_t sBl = sA + 24576;

#pragma unroll
        for (int ks = 0; ks < 2; ks++) {
            uint32_t a[4][4];
#pragma unroll
            for (int mi = 0; mi < 4; mi++) {
                int r = wm * 64 + mi * 16 + rA_l;
                int ck = ks * 2 + ckA_l;
                ldmx4(a[mi], sA + r * 64 + ((ck ^ ((r >> 1) & 3)) << 4));
            }
            uint32_t b[4][2];
            {
                int ck = ks * 2 + ckB_l;
#pragma unroll
                for (int p = 0; p < 2; p++) {
                    int r = wn * 32 + p * 16 + rB_l;
                    uint32_t d[4];
                    ldmx4(d, sBh + r * 64 + ((ck ^ ((r >> 1) & 3)) << 4));
                    b[p * 2][0] = d[0]; b[p * 2][1] = d[1];
                    b[p * 2 + 1][0] = d[2]; b[p * 2 + 1][1] = d[3];
                }
            }
#pragma unroll
            for (int mi = 0; mi < 4; mi++)
#pragma unroll
                for (int ni = 0; ni < 4; ni++) mma16816(c[mi][ni], a[mi], b[ni]);
            {
                int ck = ks * 2 + ckB_l;
#pragma unroll
                for (int p = 0; p < 2; p++) {
                    int r = wn * 32 + p * 16 + rB_l;
                    uint32_t d[4];
                    ldmx4(d, sBl + r * 64 + ((ck ^ ((r >> 1) & 3)) << 4));
                    b[p * 2][0] = d[0]; b[p * 2][1] = d[1];
                    b[p * 2 + 1][0] = d[2]; b[p * 2 + 1][1] = d[3];
                }
            }
#pragma unroll
            for (int mi = 0; mi < 4; mi++)
#pragma unroll
                for (int ni = 0; ni < 4; ni++) mma16816(c[mi][ni], a[mi], b[ni]);
        }
        __syncthreads();
        if (tid == 0 && i + 2 < nkc) {
            const int s2 = (i + 2) - ((i + 2) / 3) * 3;
            uint32_t sb = sdata + s2 * STAGE_BYTES;
            expect_tx(mb + s2 * 8, 32768u);
            bulk_g2s(sb,         Asrc  + (size_t)(i + 2) * 8192, 16384, mb + s2 * 8);
            bulk_g2s(sb + 16384, Bhsrc + (size_t)(i + 2) * 4096,  8192, mb + s2 * 8);
            bulk_g2s(sb + 24576, Blsrc + (size_t)(i + 2) * 4096,  8192, mb + s2 * 8);
        }
    }

    // epilogue
#pragma unroll
    for (int mi = 0; mi < 4; mi++) {
        int row = mt * 256 + wm * 64 + mi * 16 + (lane >> 2);
#pragma unroll
        for (int ni = 0; ni < 4; ni++) {
            int col = nt * 128 + wn * 32 + ni * 8 + (lane & 3) * 2;
            if (col < Nreal) {
                float2 bb = *(const float2*)(bias + col);
                float2 v0 = {c[mi][ni][0] + bb.x, c[mi][ni][1] + bb.y};
                float2 v1 = {c[mi][ni][2] + bb.x, c[mi][ni][3] + bb.y};
                *(float2*)(C + (size_t)row * ldc + col) = v0;
                *(float2*)(C + (size_t)(row + 8) * ldc + col) = v1;
            }
        }
    }
}

// ---------------------------------------------------------------------------
// RoPE (in place, q heads 0..63 + k heads 64..71)
// ---------------------------------------------------------------------------
__global__ void rope_kernel(float* __restrict__ qkv, const int* __restrict__ positions) {
    __shared__ float cs[32], sn[32];
    const int t = blockIdx.x;
    const int pos = positions[t] % S_LEN;
    if (threadIdx.x < 32) {
        int i = threadIdx.x;
        float freq   = powf(150000.0f, (float)i / 32.0f);
        float interp = 1.0f / (32.0f * freq);
        float extrap = 1.0f / freq;
        float lnT    = logf(150000.0f);
        float low    = 32.0f * logf(4096.0f / (32.0f * 6.2831853071795864f)) / lnT;
        float high   = 32.0f * logf(4096.0f / 6.2831853071795864f) / lnT;
        float ramp   = fminf(fmaxf(((float)i - low) / (high - low), 0.0f), 1.0f);
        float inv    = interp * ramp + extrap * (1.0f - ramp);
        float conc   = 0.1f * logf(32.0f) + 1.0f;
        float tt     = (float)pos * inv;
        cs[i] = cosf(tt) * conc;
        sn[i] = sinf(tt) * conc;
    }
    __syncthreads();
    for (int idx = threadIdx.x; idx < 72 * 32; idx += blockDim.x) {
        int head = idx >> 5;
        int i = idx & 31;
        float* base = qkv + (size_t)t * QKV_COLS + head * 64;
        float x1 = base[i], x2 = base[i + 32];
        base[i]      = x1 * cs[i] - x2 * sn[i];
        base[i + 32] = x2 * cs[i] + x1 * sn[i];
    }
}

// ---------------------------------------------------------------------------
// Sliding-window attention with sinks; writes ctx straight into packed fp16
// A-operand layout for the O projection.
// ---------------------------------------------------------------------------
__global__ void attn_kernel(const float* __restrict__ qkv,
                            const float* __restrict__ sinks,
                            __half* __restrict__ cpk) {
    extern __shared__ float sm[];
    float* ks  = sm;                  // 128*65
    float* vs  = ks + 128 * 65;       // 128*65
    float* qs  = vs + 128 * 65;       // 512
    float* sc  = qs + 512;            // 128
    float* red = sc + 128;            // 16
    float* pv  = red + 16;            // 128

    const int qi  = blockIdx.x;
    const int kh  = blockIdx.y;
    const int b   = blockIdx.z;
    const int tid = threadIdx.x;
    const int t   = b * S_LEN + qi;
    const int kstart = (qi >= WIN - 1) ? qi - (WIN - 1) : 0;
    const int cnt = qi - kstart + 1;

    for (int i = tid; i < 512; i += 128)
        qs[i] = qkv[(size_t)t * QKV_COLS + kh * 512 + i];
    for (int i = tid; i < cnt * 64; i += 128) {
        int r = i >> 6, d = i & 63;
        size_t rowbase = (size_t)(b * S_LEN + kstart + r) * QKV_COLS;
        ks[r * 65 + d] = qkv[rowbase + 4096 + kh * 64 + d];
        vs[r * 65 + d] = qkv[rowbase + 4608 + kh * 64 + d];
    }
    __syncthreads();

    const bool havek = tid < cnt;
    float kreg[64];
#pragma unroll
    for (int d = 0; d < 64; d++) kreg[d] = havek ? ks[tid * 65 + d] : 0.0f;

    for (int h8 = 0; h8 < 8; h8++) {
        const int n = kh * 8 + h8;
        float s = -1e30f;
        if (havek) {
            float acc = 0.0f;
            const float* qr = qs + h8 * 64;
#pragma unroll
            for (int d = 0; d < 64; d++) acc = fmaf(kreg[d], qr[d], acc);
            s = acc * 0.125f;
        }
        float m = s;
#pragma unroll
        for (int o = 16; o; o >>= 1) m = fmaxf(m, __shfl_xor_sync(0xffffffffu, m, o));
        if ((tid & 31) == 0) red[tid >> 5] = m;
        __syncthreads();
        m = fmaxf(fmaxf(red[0], red[1]), fmaxf(red[2], red[3]));
        const float sink = sinks[n];
        m = fmaxf(m, sink);

        float p = havek ? __expf(s - m) : 0.0f;
        sc[tid] = p;
        float ps = p;
#pragma unroll
        for (int o = 16; o; o >>= 1) ps += __shfl_xor_sync(0xffffffffu, ps, o);
        if ((tid & 31) == 0) red[4 + (tid >> 5)] = ps;
        __syncthreads();
        const float denom = red[4] + red[5] + red[6] + red[7] + __expf(sink - m);

        // PV with all 128 threads: tid>>6 selects j-parity, tid&63 selects dim
        {
            float acc = 0.0f;
            const int d = tid & 63;
            for (int j = tid >> 6; j < cnt; j += 2)
                acc = fmaf(sc[j], vs[j * 65 + d], acc);
            pv[tid] = acc;
        }
        __syncthreads();
        if (tid < 64) {
            float r = (pv[tid] + pv[tid + 64]) / denom;
            int k = n * 64 + tid;
            cpk[offA(t, k, NKC_O)] = __float2half_rn(r);
        }
        __syncthreads();
    }
}

// ---------------------------------------------------------------------------
// Launch
// ---------------------------------------------------------------------------
extern "C" void kernel_launch(void* const* d_in, const int* in_sizes, int n_in,
                              void* d_out, int out_size) {
    const float* x     = (const float*)d_in[0];
    const float* wq    = (const float*)d_in[1];
    const float* bq    = (const float*)d_in[2];
    const float* wk    = (const float*)d_in[3];
    const float* bk    = (const float*)d_in[4];
    const float* wv    = (const float*)d_in[5];
    const float* bv    = (const float*)d_in[6];
    const float* wo    = (const float*)d_in[7];
    const float* bo    = (const float*)d_in[8];
    const float* sinks = (const float*)d_in[9];
    const int* positions = (const int*)d_in[10];
    float* out = (float*)d_out;

    void *xpk, *wbh, *wbl, *wobh, *wobl, *cpk, *qkv, *biasqkv;
    cudaGetSymbolAddress(&xpk, g_xpk);
    cudaGetSymbolAddress(&wbh, g_wbh);   cudaGetSymbolAddress(&wbl, g_wbl);
    cudaGetSymbolAddress(&wobh, g_wobh); cudaGetSymbolAddress(&wobl, g_wobl);
    cudaGetSymbolAddress(&cpk, g_cpk);
    cudaGetSymbolAddress(&qkv, g_qkv);
    cudaGetSymbolAddress(&biasqkv, g_biasqkv);

    float* qkvp = (float*)qkv;

    cudaFuncSetAttribute(gemm_tc, cudaFuncAttributeMaxDynamicSharedMemorySize, GEMM_SMEM);
    const int attn_smem = (128 * 65 * 2 + 512 + 128 + 16 + 128) * (int)sizeof(float);
    cudaFuncSetAttribute(attn_kernel, cudaFuncAttributeMaxDynamicSharedMemorySize, attn_smem);

    // 1. pack inputs/weights
    pack_x<<<dim3(12, T_TOK), 256>>>(x, (__half*)xpk);
    tsp<<<dim3(128, 90), dim3(32, 8)>>>(wq, (__half*)wbh, (__half*)wbl,
                                        D_DIM, NH, NKC_QKV, 0);
    tsp<<<dim3(16, 90), dim3(32, 8)>>>(wk, (__half*)wbh, (__half*)wbl,
                                       D_DIM, KVH, NKC_QKV, NH);
    tsp<<<dim3(16, 90), dim3(32, 8)>>>(wv, (__half*)wbh, (__half*)wbl,
                                       D_DIM, KVH, NKC_QKV, NH + KVH);
    tsp<<<dim3(92, 128), dim3(32, 8)>>>(wo, (__half*)wobh, (__half*)wobl,
                                        NH, D_DIM, NKC_O, 0);
    concat_bias<<<(QKV_COLS + 255) / 256, 256>>>(bq, bk, bv, (float*)biasqkv);

    // 2. fused QKV projection
    gemm_tc<<<dim3(QKV_COLS / 128, T_TOK / 256), 512, GEMM_SMEM>>>(
        (const __half*)xpk, (const __half*)wbh, (const __half*)wbl,
        (const float*)biasqkv, qkvp, NKC_QKV, QKV_COLS, QKV_COLS);

    // 3. RoPE
    rope_kernel<<<T_TOK, 256>>>(qkvp, positions);

    // 4. attention (writes packed fp16 ctx)
    attn_kernel<<<dim3(S_LEN, 8, B_BATCH), 128, attn_smem>>>(
        qkvp, sinks, (__half*)cpk);

    // 5. output projection
    gemm_tc<<<dim3(OPAD / 128, T_TOK / 256), 512, GEMM_SMEM>>>(
        (const __half*)cpk, (const __half*)wobh, (const __half*)wobl,
        bo, out, NKC_O, D_DIM, D_DIM);
}

// round 4
// speedup vs baseline: 2.7800x; 1.5097x over previous
#include <cuda_runtime.h>
#include <cuda_fp16.h>
#include <cstdint>

// ---------------------------------------------------------------------------
// Problem constants
// ---------------------------------------------------------------------------
#define T_TOK   2048
#define D_DIM   2880
#define S_LEN   1024
#define B_BATCH 2
#define WIN     128
#define NH      4096
#define KVH     512
#define QKV_COLS 5120
#define OPAD    2944
#define NKC_QKV 90        // 2880/32
#define NKC_O   128       // 4096/32

// ---------------------------------------------------------------------------
// Scratch
// ---------------------------------------------------------------------------
__device__ __half g_xpk [(size_t)16 * NKC_QKV * 128 * 32];   // x packed fp16 (A blobs)
__device__ __half g_wbh [(size_t)40 * NKC_QKV * 128 * 32];   // qkv weights hi (B blobs)
__device__ __half g_wbl [(size_t)40 * NKC_QKV * 128 * 32];   // qkv weights lo
__device__ __half g_wobh[(size_t)23 * NKC_O   * 128 * 32];   // wo hi (single plane)
__device__ __half g_cpk [(size_t)16 * NKC_O   * 128 * 32];   // ctx packed fp16 (A blobs)
__device__ float  g_qkv [(size_t)T_TOK * QKV_COLS];
__device__ float  g_biasqkv[QKV_COLS];

// ---------------------------------------------------------------------------
// Packed layout: 128-row x 32-k tiles, row = 64B, 16B chunks XOR-swizzled by
// ((row>>1)&3) so ldmatrix is conflict-free while bulk copies stay linear.
// ---------------------------------------------------------------------------
__device__ __forceinline__ size_t offP(int r_glob, int k, int nkc) {
    int r = r_glob & 127, ck = (k >> 3) & 3, w = k & 7;
    return ((((size_t)(r_glob >> 7)) * nkc + (k >> 5)) * 128 + r) * 32 +
           (((ck ^ ((r >> 1) & 3)) << 3) + w);
}

// ---------------------------------------------------------------------------
// PTX helpers
// ---------------------------------------------------------------------------
__device__ __forceinline__ void mbar_init(uint32_t a, uint32_t cnt) {
    asm volatile("mbarrier.init.shared.b64 [%0], %1;" :: "r"(a), "r"(cnt) : "memory");
}
__device__ __forceinline__ void mbar_wait(uint32_t a, int ph) {
    uint32_t done = 0;
    while (!done) {
        asm volatile("{\n\t.reg .pred p;\n\t"
                     "mbarrier.try_wait.parity.acquire.cta.shared::cta.b64 p, [%1], %2, 0x989680;\n\t"
                     "selp.b32 %0,1,0,p;\n\t}"
                     : "=r"(done) : "r"(a), "r"((uint32_t)ph) : "memory");
    }
}
__device__ __forceinline__ void expect_tx(uint32_t a, uint32_t bytes) {
    asm volatile("mbarrier.arrive.expect_tx.shared::cta.b64 _, [%0], %1;"
                 :: "r"(a), "r"(bytes) : "memory");
}
__device__ __forceinline__ void bulk_g2s(uint32_t sdst, const void* gsrc,
                                         uint32_t bytes, uint32_t mbar) {
    asm volatile("cp.async.bulk.shared::cluster.global.mbarrier::complete_tx::bytes "
                 "[%0], [%1], %2, [%3];"
                 :: "r"(sdst), "l"(__cvta_generic_to_global(gsrc)), "r"(bytes), "r"(mbar)
                 : "memory");
}
__device__ __forceinline__ void ldmx4(uint32_t* d, uint32_t addr) {
    asm volatile("ldmatrix.sync.aligned.m8n8.x4.shared.b16 {%0,%1,%2,%3}, [%4];"
                 : "=r"(d[0]), "=r"(d[1]), "=r"(d[2]), "=r"(d[3]) : "r"(addr));
}
__device__ __forceinline__ void mma16816(float* c, const uint32_t* a, const uint32_t* b) {
    asm volatile(
        "mma.sync.aligned.m16n8k16.row.col.f32.f16.f16.f32 "
        "{%0,%1,%2,%3},{%4,%5,%6,%7},{%8,%9},{%0,%1,%2,%3};\n"
        : "+f"(c[0]), "+f"(c[1]), "+f"(c[2]), "+f"(c[3])
        : "r"(a[0]), "r"(a[1]), "r"(a[2]), "r"(a[3]), "r"(b[0]), "r"(b[1]));
}

// fast exp on the FMA pipe (x <= 0 path), rel err ~1e-7
__device__ __forceinline__ float fexp(float x) {
    x = fmaxf(x, -87.0f);
    float y = x * 1.44269504f;
    float n = rintf(y);
    float f = y - n;
    float p = 1.33336498e-3f;
    p = fmaf(p, f, 9.61011233e-3f);
    p = fmaf(p, f, 5.55040755e-2f);
    p = fmaf(p, f, 2.40226507e-1f);
    p = fmaf(p, f, 6.93147182e-1f);
    p = fmaf(p, f, 1.0f);
    return p * __int_as_float(((int)n + 127) << 23);
}

// ---------------------------------------------------------------------------
// Prep kernels
// ---------------------------------------------------------------------------
__global__ void pack_x(const float* __restrict__ x, __half* __restrict__ o) {
    int k = blockIdx.x * 256 + threadIdx.x;
    int t = blockIdx.y;
    if (k < D_DIM)
        o[offP(t, k, NKC_QKV)] = __float2half_rn(x[(size_t)t * D_DIM + k]);
}

// transpose + 2-plane split (qkv weights)
__global__ void tsp(const float* __restrict__ in, __half* __restrict__ oh,
                    __half* __restrict__ ol, int R, int C, int nkc, int nbase) {
    __shared__ float tb[32][33];
    int c0 = blockIdx.x * 32, r0 = blockIdx.y * 32;
    int tx = threadIdx.x, ty = threadIdx.y;
#pragma unroll
    for (int i = 0; i < 4; i++) {
        int r = r0 + ty + i * 8, c = c0 + tx;
        tb[ty + i * 8][tx] = (c < C) ? in[(size_t)r * C + c] : 0.0f;
    }
    __syncthreads();
#pragma unroll
    for (int i = 0; i < 4; i++) {
        int n = nbase + c0 + ty + i * 8, k = r0 + tx;
        float v = tb[tx][ty + i * 8];
        __half h = __float2half_rn(v);
        size_t o = offP(n, k, nkc);
        oh[o] = h;
        ol[o] = __float2half_rn(v - __half2float(h));
    }
}

// transpose single-plane (wo)
__global__ void tsp1(const float* __restrict__ in, __half* __restrict__ oh,
                     int R, int C, int nkc) {
    __shared__ float tb[32][33];
    int c0 = blockIdx.x * 32, r0 = blockIdx.y * 32;
    int tx = threadIdx.x, ty = threadIdx.y;
#pragma unroll
    for (int i = 0; i < 4; i++) {
        int r = r0 + ty + i * 8, c = c0 + tx;
        tb[ty + i * 8][tx] = (c < C) ? in[(size_t)r * C + c] : 0.0f;
    }
    __syncthreads();
#pragma unroll
    for (int i = 0; i < 4; i++) {
        int n = c0 + ty + i * 8, k = r0 + tx;
        oh[offP(n, k, nkc)] = __float2half_rn(tb[tx][ty + i * 8]);
    }
}

__global__ void concat_bias(const float* __restrict__ bq, const float* __restrict__ bk,
                            const float* __restrict__ bv, float* __restrict__ out) {
    int i = blockIdx.x * blockDim.x + threadIdx.x;
    if (i < QKV_COLS)
        out[i] = (i < NH) ? bq[i] : (i < NH + KVH ? bk[i - NH] : bv[i - NH - KVH]);
}

// ---------------------------------------------------------------------------
// GEMM: 128x128 CTA tile, 256 threads (8 warps of 64x32), 2 CTAs/SM,
// 3-stage cp.async.bulk pipeline. two_term selects (Bh+Bl) vs Bh only.
// ---------------------------------------------------------------------------
#define STAGE_BYTES 24576
#define GEMM_SMEM   (128 + 3 * STAGE_BYTES)

__global__ __launch_bounds__(256, 2) void gemm_tc(
    const __half* __restrict__ Apk, const __half* __restrict__ Bhp,
    const __half* __restrict__ Blp, const float* __restrict__ bias,
    float* __restrict__ C, int nkc, int Nreal, int ldc, int two_term)
{
    extern __shared__ __align__(128) uint8_t dsm[];
    const uint32_t base = (uint32_t)__cvta_generic_to_shared(dsm);
    const uint32_t mb = base;
    const uint32_t sdata = base + 128;

    const int tid = threadIdx.x, lane = tid & 31, warp = tid >> 5;
    const int wm = warp >> 2, wn = warp & 3;
    const int mt = blockIdx.y, nt = blockIdx.x;

    if (tid == 0) { mbar_init(mb, 1); mbar_init(mb + 8, 1); mbar_init(mb + 16, 1); }
    __syncthreads();

    const __half* Asrc  = Apk + (size_t)mt * nkc * 4096;
    const __half* Bhsrc = Bhp + (size_t)nt * nkc * 4096;
    const __half* Blsrc = Blp + (size_t)nt * nkc * 4096;
    const uint32_t txb = two_term ? 24576u : 16384u;

    float c[4][4][4];
#pragma unroll
    for (int mi = 0; mi < 4; mi++)
#pragma unroll
        for (int ni = 0; ni < 4; ni++)
#pragma unroll
            for (int r = 0; r < 4; r++) c[mi][ni][r] = 0.0f;

    if (tid == 0) {
#pragma unroll
        for (int s = 0; s < 2; s++) {
            uint32_t sb = sdata + s * STAGE_BYTES;
            expect_tx(mb + s * 8, txb);
            bulk_g2s(sb,        Asrc  + (size_t)s * 4096, 8192, mb + s * 8);
            bulk_g2s(sb + 8192, Bhsrc + (size_t)s * 4096, 8192, mb + s * 8);
            if (two_term)
                bulk_g2s(sb + 16384, Blsrc + (size_t)s * 4096, 8192, mb + s * 8);
        }
    }

    const int rA_l = lane & 15;
    const int ckA_l = lane >> 4;
    const int rB_l = (lane & 7) + ((lane >> 4) << 3);
    const int ckB_l = (lane >> 3) & 1;

    for (int i = 0; i < nkc; i++) {
        const int s = i - (i / 3) * 3;
        const int ph = (i / 3) & 1;
        mbar_wait(mb + s * 8, ph);

        const uint32_t sA  = sdata + s * STAGE_BYTES;
        const uint32_t sBh = sA + 8192;
        const uint32_t sBl = sA + 16384;

#pragma unroll
        for (int ks = 0; ks < 2; ks++) {
            uint32_t a[4][4];
#pragma unroll
            for (int mi = 0; mi < 4; mi++) {
                int r = wm * 64 + mi * 16 + rA_l;
                int ck = ks * 2 + ckA_l;
                ldmx4(a[mi], sA + r * 64 + ((ck ^ ((r >> 1) & 3)) << 4));
            }
            uint32_t b[4][2];
            {
                int ck = ks * 2 + ckB_l;
#pragma unroll
                for (int p = 0; p < 2; p++) {
                    int r = wn * 32 + p * 16 + rB_l;
                    uint32_t d[4];
                    ldmx4(d, sBh + r * 64 + ((ck ^ ((r >> 1) & 3)) << 4));
                    b[p * 2][0] = d[0]; b[p * 2][1] = d[1];
                    b[p * 2 + 1][0] = d[2]; b[p * 2 + 1][1] = d[3];
                }
            }
#pragma unroll
            for (int mi = 0; mi < 4; mi++)
#pragma unroll
                for (int ni = 0; ni < 4; ni++) mma16816(c[mi][ni], a[mi], b[ni]);
            if (two_term) {
                int ck = ks * 2 + ckB_l;
#pragma unroll
                for (int p = 0; p < 2; p++) {
                    int r = wn * 32 + p * 16 + rB_l;
                    uint32_t d[4];
                    ldmx4(d, sBl + r * 64 + ((ck ^ ((r >> 1) & 3)) << 4));
                    b[p * 2][0] = d[0]; b[p * 2][1] = d[1];
                    b[p * 2 + 1][0] = d[2]; b[p * 2 + 1][1] = d[3];
                }
#pragma unroll
                for (int mi = 0; mi < 4; mi++)
#pragma unroll
                    for (int ni = 0; ni < 4; ni++) mma16816(c[mi][ni], a[mi], b[ni]);
            }
        }
        __syncthreads();
        if (tid == 0 && i + 2 < nkc) {
            const int s2 = (i + 2) - ((i + 2) / 3) * 3;
            uint32_t sb = sdata + s2 * STAGE_BYTES;
            expect_tx(mb + s2 * 8, txb);
            bulk_g2s(sb,        Asrc  + (size_t)(i + 2) * 4096, 8192, mb + s2 * 8);
            bulk_g2s(sb + 8192, Bhsrc + (size_t)(i + 2) * 4096, 8192, mb + s2 * 8);
            if (two_term)
                bulk_g2s(sb + 16384, Blsrc + (size_t)(i + 2) * 4096, 8192, mb + s2 * 8);
        }
    }

#pragma unroll
    for (int mi = 0; mi < 4; mi++) {
        int row = mt * 128 + wm * 64 + mi * 16 + (lane >> 2);
#pragma unroll
        for (int ni = 0; ni < 4; ni++) {
            int col = nt * 128 + wn * 32 + ni * 8 + (lane & 3) * 2;
            if (col < Nreal) {
                float2 bb = *(const float2*)(bias + col);
                float2 v0 = {c[mi][ni][0] + bb.x, c[mi][ni][1] + bb.y};
                float2 v1 = {c[mi][ni][2] + bb.x, c[mi][ni][3] + bb.y};
                *(float2*)(C + (size_t)row * ldc + col) = v0;
                *(float2*)(C + (size_t)(row + 8) * ldc + col) = v1;
            }
        }
    }
}

// ---------------------------------------------------------------------------
// RoPE (in place on q heads 0..63 + k heads 64..71)
// ---------------------------------------------------------------------------
__global__ void rope_kernel(float* __restrict__ qkv, const int* __restrict__ positions) {
    __shared__ float cs[32], sn[32];
    const int t = blockIdx.x;
    const int pos = positions[t] % S_LEN;
    if (threadIdx.x < 32) {
        int i = threadIdx.x;
        float freq   = powf(150000.0f, (float)i / 32.0f);
        float interp = 1.0f / (32.0f * freq);
        float extrap = 1.0f / freq;
        float lnT    = logf(150000.0f);
        float low    = 32.0f * logf(4096.0f / (32.0f * 6.2831853071795864f)) / lnT;
        float high   = 32.0f * logf(4096.0f / 6.2831853071795864f) / lnT;
        float ramp   = fminf(fmaxf(((float)i - low) / (high - low), 0.0f), 1.0f);
        float inv    = interp * ramp + extrap * (1.0f - ramp);
        float conc   = 0.1f * logf(32.0f) + 1.0f;
        float tt     = (float)pos * inv;
        cs[i] = cosf(tt) * conc;
        sn[i] = sinf(tt) * conc;
    }
    __syncthreads();
    for (int idx = threadIdx.x; idx < 72 * 32; idx += blockDim.x) {
        int head = idx >> 5;
        int i = idx & 31;
        float* base = qkv + (size_t)t * QKV_COLS + head * 64;
        float x1 = base[i], x2 = base[i + 32];
        base[i]      = x1 * cs[i] - x2 * sn[i];
        base[i + 32] = x2 * cs[i] + x1 * sn[i];
    }
}

// ---------------------------------------------------------------------------
// Attention: 4 queries x 1 kv-head per block, 160 threads.
// K/V union window (<=131 rows) staged once; K rows register-cached per
// thread; polynomial exp; per-warp PV with float2 V reads; ctx written
// directly to the packed fp16 A-blob layout of the O projection.
// ---------------------------------------------------------------------------
#define KV_PITCH 66
#define ATTN_SMEM ((131 * KV_PITCH * 2 + 2048 + 4 * 160 + 64) * 4)

__global__ __launch_bounds__(160) void attn_kernel(
    const float* __restrict__ qkv, const float* __restrict__ sinks,
    __half* __restrict__ cpk)
{
    extern __shared__ float sm[];
    float* ks   = sm;                          // 131*66
    float* vs   = ks + 131 * KV_PITCH;         // 131*66
    float* qsm  = vs + 131 * KV_PITCH;         // 2048: [h8][d][qq] float4-packed
    float* sc   = qsm + 2048;                  // 4*160
    float* redm = sc + 4 * 160;                // 32
    float* reds = redm + 32;                   // 32

    const int q0  = blockIdx.x * 4;
    const int kh  = blockIdx.y;
    const int b   = blockIdx.z;
    const int tid = threadIdx.x;
    const int lane = tid & 31, w = tid >> 5;
    const int kstartU = (q0 >= 127) ? q0 - 127 : 0;
    const int cntU = q0 + 3 - kstartU + 1;

    // stage Q (float4-packed over qq) and K/V union window
    for (int i = tid; i < 2048; i += 160) {
        int qq = i >> 9, r = i & 511;
        qsm[r * 4 + qq] = qkv[(size_t)(b * S_LEN + q0 + qq) * QKV_COLS + kh * 512 + r];
    }
    for (int i = tid; i < cntU * 64; i += 160) {
        int r = i >> 6, d = i & 63;
        size_t rb = (size_t)(b * S_LEN + kstartU + r) * QKV_COLS;
        ks[r * KV_PITCH + d] = qkv[rb + 4096 + kh * 64 + d];
        vs[r * KV_PITCH + d] = qkv[rb + 4608 + kh * 64 + d];
    }
    __syncthreads();

    const bool havek = tid < cntU;
    float kreg[64];
#pragma unroll
    for (int d = 0; d < 64; d++) kreg[d] = havek ? ks[tid * KV_PITCH + d] : 0.0f;
    const int kpos = kstartU + tid;

    for (int h8 = 0; h8 < 8; h8++) {
        const float sink = sinks[kh * 8 + h8];
        float s[4] = {-1e30f, -1e30f, -1e30f, -1e30f};
        if (havek) {
            float a0 = 0.f, a1 = 0.f, a2 = 0.f, a3 = 0.f;
            const float4* qp = (const float4*)(qsm + h8 * 256);
#pragma unroll
            for (int d = 0; d < 64; d++) {
                float4 qv = qp[d];
                float kd = kreg[d];
                a0 = fmaf(kd, qv.x, a0);
                a1 = fmaf(kd, qv.y, a1);
                a2 = fmaf(kd, qv.z, a2);
                a3 = fmaf(kd, qv.w, a3);
            }
            float aa[4] = {a0, a1, a2, a3};
#pragma unroll
            for (int qq = 0; qq < 4; qq++) {
                int qg = q0 + qq;
                int loG = qg - 127; if (loG < 0) loG = 0;
                s[qq] = (kpos >= loG && kpos <= qg) ? aa[qq] * 0.125f : -1e30f;
            }
        }
        // batched warp max
#pragma unroll
        for (int qq = 0; qq < 4; qq++) {
            float m = s[qq];
#pragma unroll
            for (int o = 16; o; o >>= 1) m = fmaxf(m, __shfl_xor_sync(0xffffffffu, m, o));
            if (lane == 0) redm[qq * 8 + w] = m;
        }
        __syncthreads();
        float mq[4], denomq[4];
#pragma unroll
        for (int qq = 0; qq < 4; qq++) {
            float m = redm[qq * 8];
#pragma unroll
            for (int j = 1; j < 5; j++) m = fmaxf(m, redm[qq * 8 + j]);
            mq[qq] = fmaxf(m, sink);
        }
        // p + batched warp sum
#pragma unroll
        for (int qq = 0; qq < 4; qq++) {
            float p = fexp(s[qq] - mq[qq]);
            sc[qq * 160 + tid] = p;
#pragma unroll
            for (int o = 16; o; o >>= 1) p += __shfl_xor_sync(0xffffffffu, p, o);
            if (lane == 0) reds[qq * 8 + w] = p;
        }
        __syncthreads();
#pragma unroll
        for (int qq = 0; qq < 4; qq++) {
            float sum = reds[qq * 8] + reds[qq * 8 + 1] + reds[qq * 8 + 2] +
                        reds[qq * 8 + 3] + reds[qq * 8 + 4];
            denomq[qq] = sum + fexp(sink - mq[qq]);
        }
        // PV: warp w (<4) owns query qq = w; lanes own d pairs
        if (w < 4) {
            const int qg = q0 + w;
            int loG = qg - 127; if (loG < 0) loG = 0;
            const int lo = loG - kstartU, hi = qg - kstartU;
            float2 acc = {0.f, 0.f};
            const float* scw = sc + w * 160;
            const float* vb = vs + lane * 2;
            for (int j = lo; j <= hi; j++) {
                float p = scw[j];
                float2 v = *(const float2*)(vb + j * KV_PITCH);
                acc.x = fmaf(p, v.x, acc.x);
                acc.y = fmaf(p, v.y, acc.y);
            }
            float inv = 1.0f / denomq[w];
            int t = b * S_LEN + qg;
            int kcol = (kh * 8 + h8) * 64 + lane * 2;
            size_t o = offP(t, kcol, NKC_O);
            *(__half2*)(cpk + o) = __floats2half2_rn(acc.x * inv, acc.y * inv);
        }
        __syncthreads();   // protect sc/redm/reds before next head
    }
}

// ---------------------------------------------------------------------------
// Launch
// ---------------------------------------------------------------------------
extern "C" void kernel_launch(void* const* d_in, const int* in_sizes, int n_in,
                              void* d_out, int out_size) {
    const float* x     = (const float*)d_in[0];
    const float* wq    = (const float*)d_in[1];
    const float* bq    = (const float*)d_in[2];
    const float* wk    = (const float*)d_in[3];
    const float* bk    = (const float*)d_in[4];
    const float* wv    = (const float*)d_in[5];
    const float* bv    = (const float*)d_in[6];
    const float* wo    = (const float*)d_in[7];
    const float* bo    = (const float*)d_in[8];
    const float* sinks = (const float*)d_in[9];
    const int* positions = (const int*)d_in[10];
    float* out = (float*)d_out;

    void *xpk, *wbh, *wbl, *wobh, *cpk, *qkv, *biasqkv;
    cudaGetSymbolAddress(&xpk, g_xpk);
    cudaGetSymbolAddress(&wbh, g_wbh);   cudaGetSymbolAddress(&wbl, g_wbl);
    cudaGetSymbolAddress(&wobh, g_wobh);
    cudaGetSymbolAddress(&cpk, g_cpk);
    cudaGetSymbolAddress(&qkv, g_qkv);
    cudaGetSymbolAddress(&biasqkv, g_biasqkv);

    float* qkvp = (float*)qkv;

    cudaFuncSetAttribute(gemm_tc, cudaFuncAttributeMaxDynamicSharedMemorySize, GEMM_SMEM);
    cudaFuncSetAttribute(attn_kernel, cudaFuncAttributeMaxDynamicSharedMemorySize, ATTN_SMEM);

    // 1. pack inputs/weights
    pack_x<<<dim3(12, T_TOK), 256>>>(x, (__half*)xpk);
    tsp<<<dim3(128, 90), dim3(32, 8)>>>(wq, (__half*)wbh, (__half*)wbl,
                                        D_DIM, NH, NKC_QKV, 0);
    tsp<<<dim3(16, 90), dim3(32, 8)>>>(wk, (__half*)wbh, (__half*)wbl,
                                       D_DIM, KVH, NKC_QKV, NH);
    tsp<<<dim3(16, 90), dim3(32, 8)>>>(wv, (__half*)wbh, (__half*)wbl,
                                       D_DIM, KVH, NKC_QKV, NH + KVH);
    tsp1<<<dim3(92, 128), dim3(32, 8)>>>(wo, (__half*)wobh, NH, D_DIM, NKC_O);
    concat_bias<<<(QKV_COLS + 255) / 256, 256>>>(bq, bk, bv, (float*)biasqkv);

    // 2. fused QKV projection (2-term split weights)
    gemm_tc<<<dim3(QKV_COLS / 128, T_TOK / 128), 256, GEMM_SMEM>>>(
        (const __half*)xpk, (const __half*)wbh, (const __half*)wbl,
        (const float*)biasqkv, qkvp, NKC_QKV, QKV_COLS, QKV_COLS, 1);

    // 3. RoPE
    rope_kernel<<<T_TOK, 256>>>(qkvp, positions);

    // 4. attention (writes packed fp16 ctx)
    attn_kernel<<<dim3(S_LEN / 4, 8, B_BATCH), 160, ATTN_SMEM>>>(
        qkvp, sinks, (__half*)cpk);

    // 5. output projection (single-term)
    gemm_tc<<<dim3(OPAD / 128, T_TOK / 128), 256, GEMM_SMEM>>>(
        (const __half*)cpk, (const __half*)wobh, (const __half*)wobh,
        bo, out, NKC_O, D_DIM, D_DIM, 0);
}

// round 6
// speedup vs baseline: 3.1705x; 1.1405x over previous
#include <cuda_runtime.h>
#include <cuda_fp16.h>
#include <cstdint>

// ---------------------------------------------------------------------------
// Problem constants
// ---------------------------------------------------------------------------
#define T_TOK   2048
#define D_DIM   2880
#define S_LEN   1024
#define B_BATCH 2
#define WIN     128
#define NH      4096
#define KVH     512
#define QKV_COLS 5120
#define OPAD    2944
#define NKC_QKV 90        // 2880/32
#define NKC_O   128       // 4096/32

// ---------------------------------------------------------------------------
// Scratch
// ---------------------------------------------------------------------------
__device__ __half g_xpk [(size_t)16 * NKC_QKV * 128 * 32];   // x packed fp16 (A blobs)
__device__ __half g_wbh [(size_t)40 * NKC_QKV * 128 * 32];   // qkv weights (B blobs)
__device__ __half g_wobh[(size_t)23 * NKC_O   * 128 * 32];   // wo (B blobs)
__device__ __half g_cpk [(size_t)16 * NKC_O   * 128 * 32];   // ctx packed fp16 (A blobs)
__device__ float  g_qkv [(size_t)T_TOK * QKV_COLS];
__device__ float  g_biasqkv[QKV_COLS];

// ---------------------------------------------------------------------------
// Packed layout: 128-row x 32-k tiles, row = 64B, 16B chunks XOR-swizzled by
// ((row>>1)&3) so ldmatrix is conflict-free while bulk copies stay linear.
// ---------------------------------------------------------------------------
__device__ __forceinline__ size_t offP(int r_glob, int k, int nkc) {
    int r = r_glob & 127, ck = (k >> 3) & 3, w = k & 7;
    return ((((size_t)(r_glob >> 7)) * nkc + (k >> 5)) * 128 + r) * 32 +
           (((ck ^ ((r >> 1) & 3)) << 3) + w);
}

// ---------------------------------------------------------------------------
// PTX helpers
// ---------------------------------------------------------------------------
__device__ __forceinline__ void mbar_init(uint32_t a, uint32_t cnt) {
    asm volatile("mbarrier.init.shared.b64 [%0], %1;" :: "r"(a), "r"(cnt) : "memory");
}
__device__ __forceinline__ void mbar_wait(uint32_t a, int ph) {
    uint32_t done = 0;
    while (!done) {
        asm volatile("{\n\t.reg .pred p;\n\t"
                     "mbarrier.try_wait.parity.acquire.cta.shared::cta.b64 p, [%1], %2, 0x989680;\n\t"
                     "selp.b32 %0,1,0,p;\n\t}"
                     : "=r"(done) : "r"(a), "r"((uint32_t)ph) : "memory");
    }
}
__device__ __forceinline__ void expect_tx(uint32_t a, uint32_t bytes) {
    asm volatile("mbarrier.arrive.expect_tx.shared::cta.b64 _, [%0], %1;"
                 :: "r"(a), "r"(bytes) : "memory");
}
__device__ __forceinline__ void bulk_g2s(uint32_t sdst, const void* gsrc,
                                         uint32_t bytes, uint32_t mbar) {
    asm volatile("cp.async.bulk.shared::cluster.global.mbarrier::complete_tx::bytes "
                 "[%0], [%1], %2, [%3];"
                 :: "r"(sdst), "l"(__cvta_generic_to_global(gsrc)), "r"(bytes), "r"(mbar)
                 : "memory");
}
__device__ __forceinline__ void ldmx4(uint32_t* d, uint32_t addr) {
    asm volatile("ldmatrix.sync.aligned.m8n8.x4.shared.b16 {%0,%1,%2,%3}, [%4];"
                 : "=r"(d[0]), "=r"(d[1]), "=r"(d[2]), "=r"(d[3]) : "r"(addr));
}
__device__ __forceinline__ void mma16816(float* c, const uint32_t* a, const uint32_t* b) {
    asm volatile(
        "mma.sync.aligned.m16n8k16.row.col.f32.f16.f16.f32 "
        "{%0,%1,%2,%3},{%4,%5,%6,%7},{%8,%9},{%0,%1,%2,%3};\n"
        : "+f"(c[0]), "+f"(c[1]), "+f"(c[2]), "+f"(c[3])
        : "r"(a[0]), "r"(a[1]), "r"(a[2]), "r"(a[3]), "r"(b[0]), "r"(b[1]));
}

// fast exp on the FMA pipe (x <= 0 path), rel err ~1e-7
__device__ __forceinline__ float fexp(float x) {
    x = fmaxf(x, -87.0f);
    float y = x * 1.44269504f;
    float n = rintf(y);
    float f = y - n;
    float p = 1.33336498e-3f;
    p = fmaf(p, f, 9.61011233e-3f);
    p = fmaf(p, f, 5.55040755e-2f);
    p = fmaf(p, f, 2.40226507e-1f);
    p = fmaf(p, f, 6.93147182e-1f);
    p = fmaf(p, f, 1.0f);
    return p * __int_as_float(((int)n + 127) << 23);
}

// ---------------------------------------------------------------------------
// Prep kernels
// ---------------------------------------------------------------------------
__global__ void pack_x(const float* __restrict__ x, __half* __restrict__ o) {
    int k = blockIdx.x * 256 + threadIdx.x;
    int t = blockIdx.y;
    if (k < D_DIM)
        o[offP(t, k, NKC_QKV)] = __float2half_rn(x[(size_t)t * D_DIM + k]);
}

// transpose single-plane into packed B layout
__global__ void tsp1(const float* __restrict__ in, __half* __restrict__ oh,
                     int R, int C, int nkc, int nbase) {
    __shared__ float tb[32][33];
    int c0 = blockIdx.x * 32, r0 = blockIdx.y * 32;
    int tx = threadIdx.x, ty = threadIdx.y;
#pragma unroll
    for (int i = 0; i < 4; i++) {
        int r = r0 + ty + i * 8, c = c0 + tx;
        tb[ty + i * 8][tx] = (c < C) ? in[(size_t)r * C + c] : 0.0f;
    }
    __syncthreads();
#pragma unroll
    for (int i = 0; i < 4; i++) {
        int n = nbase + c0 + ty + i * 8, k = r0 + tx;
        oh[offP(n, k, nkc)] = __float2half_rn(tb[tx][ty + i * 8]);
    }
}

__global__ void concat_bias(const float* __restrict__ bq, const float* __restrict__ bk,
                            const float* __restrict__ bv, float* __restrict__ out) {
    int i = blockIdx.x * blockDim.x + threadIdx.x;
    if (i < QKV_COLS)
        out[i] = (i < NH) ? bq[i] : (i < NH + KVH ? bk[i - NH] : bv[i - NH - KVH]);
}

// ---------------------------------------------------------------------------
// GEMM: 128x128 CTA tile, 256 threads (8 warps of 64x32), 2 CTAs/SM,
// 4-stage cp.async.bulk pipeline (depth-3 prefetch), single fp16 term.
// ---------------------------------------------------------------------------
#define STAGE_BYTES 16384
#define NSTAGE      4
#define GEMM_SMEM   (128 + NSTAGE * STAGE_BYTES)

__global__ __launch_bounds__(256, 2) void gemm_tc(
    const __half* __restrict__ Apk, const __half* __restrict__ Bhp,
    const float* __restrict__ bias, float* __restrict__ C,
    int nkc, int Nreal, int ldc)
{
    extern __shared__ __align__(128) uint8_t dsm[];
    const uint32_t base = (uint32_t)__cvta_generic_to_shared(dsm);
    const uint32_t mb = base;
    const uint32_t sdata = base + 128;

    const int tid = threadIdx.x, lane = tid & 31, warp = tid >> 5;
    const int wm = warp >> 2, wn = warp & 3;
    const int mt = blockIdx.y, nt = blockIdx.x;

    if (tid == 0)
#pragma unroll
        for (int s = 0; s < NSTAGE; s++) mbar_init(mb + s * 8, 1);
    __syncthreads();

    const __half* Asrc = Apk + (size_t)mt * nkc * 4096;
    const __half* Bsrc = Bhp + (size_t)nt * nkc * 4096;

    float c[4][4][4];
#pragma unroll
    for (int mi = 0; mi < 4; mi++)
#pragma unroll
        for (int ni = 0; ni < 4; ni++)
#pragma unroll
            for (int r = 0; r < 4; r++) c[mi][ni][r] = 0.0f;

    if (tid == 0) {
#pragma unroll
        for (int s = 0; s < 3; s++) {
            uint32_t sb = sdata + s * STAGE_BYTES;
            expect_tx(mb + s * 8, 16384u);
            bulk_g2s(sb,        Asrc + (size_t)s * 4096, 8192, mb + s * 8);
            bulk_g2s(sb + 8192, Bsrc + (size_t)s * 4096, 8192, mb + s * 8);
        }
    }

    const int rA_l = lane & 15;
    const int ckA_l = lane >> 4;
    const int rB_l = (lane & 7) + ((lane >> 4) << 3);
    const int ckB_l = (lane >> 3) & 1;

    for (int i = 0; i < nkc; i++) {
        const int s = i & (NSTAGE - 1);
        const int ph = (i >> 2) & 1;
        mbar_wait(mb + s * 8, ph);

        const uint32_t sA = sdata + s * STAGE_BYTES;
        const uint32_t sB = sA + 8192;

#pragma unroll
        for (int ks = 0; ks < 2; ks++) {
            uint32_t a[4][4];
#pragma unroll
            for (int mi = 0; mi < 4; mi++) {
                int r = wm * 64 + mi * 16 + rA_l;
                int ck = ks * 2 + ckA_l;
                ldmx4(a[mi], sA + r * 64 + ((ck ^ ((r >> 1) & 3)) << 4));
            }
            uint32_t b[4][2];
            {
                int ck = ks * 2 + ckB_l;
#pragma unroll
                for (int p = 0; p < 2; p++) {
                    int r = wn * 32 + p * 16 + rB_l;
                    uint32_t d[4];
                    ldmx4(d, sB + r * 64 + ((ck ^ ((r >> 1) & 3)) << 4));
                    b[p * 2][0] = d[0]; b[p * 2][1] = d[1];
                    b[p * 2 + 1][0] = d[2]; b[p * 2 + 1][1] = d[3];
                }
            }
#pragma unroll
            for (int mi = 0; mi < 4; mi++)
#pragma unroll
                for (int ni = 0; ni < 4; ni++) mma16816(c[mi][ni], a[mi], b[ni]);
        }
        __syncthreads();
        if (tid == 0 && i + 3 < nkc) {
            const int s2 = (i + 3) & (NSTAGE - 1);
            uint32_t sb = sdata + s2 * STAGE_BYTES;
            expect_tx(mb + s2 * 8, 16384u);
            bulk_g2s(sb,        Asrc + (size_t)(i + 3) * 4096, 8192, mb + s2 * 8);
            bulk_g2s(sb + 8192, Bsrc + (size_t)(i + 3) * 4096, 8192, mb + s2 * 8);
        }
    }

#pragma unroll
    for (int mi = 0; mi < 4; mi++) {
        int row = mt * 128 + wm * 64 + mi * 16 + (lane >> 2);
#pragma unroll
        for (int ni = 0; ni < 4; ni++) {
            int col = nt * 128 + wn * 32 + ni * 8 + (lane & 3) * 2;
            if (col < Nreal) {
                float2 bb = *(const float2*)(bias + col);
                float2 v0 = {c[mi][ni][0] + bb.x, c[mi][ni][1] + bb.y};
                float2 v1 = {c[mi][ni][2] + bb.x, c[mi][ni][3] + bb.y};
                *(float2*)(C + (size_t)row * ldc + col) = v0;
                *(float2*)(C + (size_t)(row + 8) * ldc + col) = v1;
            }
        }
    }
}

// ---------------------------------------------------------------------------
// RoPE (in place on q heads 0..63 + k heads 64..71)
// ---------------------------------------------------------------------------
__global__ void rope_kernel(float* __restrict__ qkv, const int* __restrict__ positions) {
    __shared__ float cs[32], sn[32];
    const int t = blockIdx.x;
    const int pos = positions[t] % S_LEN;
    if (threadIdx.x < 32) {
        int i = threadIdx.x;
        float freq   = powf(150000.0f, (float)i / 32.0f);
        float interp = 1.0f / (32.0f * freq);
        float extrap = 1.0f / freq;
        float lnT    = logf(150000.0f);
        float low    = 32.0f * logf(4096.0f / (32.0f * 6.2831853071795864f)) / lnT;
        float high   = 32.0f * logf(4096.0f / 6.2831853071795864f) / lnT;
        float ramp   = fminf(fmaxf(((float)i - low) / (high - low), 0.0f), 1.0f);
        float inv    = interp * ramp + extrap * (1.0f - ramp);
        float conc   = 0.1f * logf(32.0f) + 1.0f;
        float tt     = (float)pos * inv;
        cs[i] = cosf(tt) * conc;
        sn[i] = sinf(tt) * conc;
    }
    __syncthreads();
    for (int idx = threadIdx.x; idx < 72 * 32; idx += blockDim.x) {
        int head = idx >> 5;
        int i = idx & 31;
        float* base = qkv + (size_t)t * QKV_COLS + head * 64;
        float x1 = base[i], x2 = base[i + 32];
        base[i]      = x1 * cs[i] - x2 * sn[i];
        base[i + 32] = x2 * cs[i] + x1 * sn[i];
    }
}

// ---------------------------------------------------------------------------
// Attention: 4 queries x 1 kv-head per block, 160 threads.
// ---------------------------------------------------------------------------
#define KV_PITCH 66
#define ATTN_SMEM ((131 * KV_PITCH * 2 + 2048 + 4 * 160 + 64) * 4)

__global__ __launch_bounds__(160) void attn_kernel(
    const float* __restrict__ qkv, const float* __restrict__ sinks,
    __half* __restrict__ cpk)
{
    extern __shared__ float sm[];
    float* ks   = sm;                          // 131*66
    float* vs   = ks + 131 * KV_PITCH;         // 131*66
    float* qsm  = vs + 131 * KV_PITCH;         // 2048
    float* sc   = qsm + 2048;                  // 4*160
    float* redm = sc + 4 * 160;                // 32
    float* reds = redm + 32;                   // 32

    const int q0  = blockIdx.x * 4;
    const int kh  = blockIdx.y;
    const int b   = blockIdx.z;
    const int tid = threadIdx.x;
    const int lane = tid & 31, w = tid >> 5;
    const int kstartU = (q0 >= 127) ? q0 - 127 : 0;
    const int cntU = q0 + 3 - kstartU + 1;

    for (int i = tid; i < 2048; i += 160) {
        int qq = i >> 9, r = i & 511;
        qsm[r * 4 + qq] = qkv[(size_t)(b * S_LEN + q0 + qq) * QKV_COLS + kh * 512 + r];
    }
    for (int i = tid; i < cntU * 64; i += 160) {
        int r = i >> 6, d = i & 63;
        size_t rb = (size_t)(b * S_LEN + kstartU + r) * QKV_COLS;
        ks[r * KV_PITCH + d] = qkv[rb + 4096 + kh * 64 + d];
        vs[r * KV_PITCH + d] = qkv[rb + 4608 + kh * 64 + d];
    }
    __syncthreads();

    const bool havek = tid < cntU;
    float kreg[64];
#pragma unroll
    for (int d = 0; d < 64; d++) kreg[d] = havek ? ks[tid * KV_PITCH + d] : 0.0f;
    const int kpos = kstartU + tid;

    for (int h8 = 0; h8 < 8; h8++) {
        const float sink = sinks[kh * 8 + h8];
        float s[4] = {-1e30f, -1e30f, -1e30f, -1e30f};
        if (havek) {
            float a0 = 0.f, a1 = 0.f, a2 = 0.f, a3 = 0.f;
            const float4* qp = (const float4*)(qsm + h8 * 256);
#pragma unroll
            for (int d = 0; d < 64; d++) {
                float4 qv = qp[d];
                float kd = kreg[d];
                a0 = fmaf(kd, qv.x, a0);
                a1 = fmaf(kd, qv.y, a1);
                a2 = fmaf(kd, qv.z, a2);
                a3 = fmaf(kd, qv.w, a3);
            }
            float aa[4] = {a0, a1, a2, a3};
#pragma unroll
            for (int qq = 0; qq < 4; qq++) {
                int qg = q0 + qq;
                int loG = qg - 127; if (loG < 0) loG = 0;
                s[qq] = (kpos >= loG && kpos <= qg) ? aa[qq] * 0.125f : -1e30f;
            }
        }
#pragma unroll
        for (int qq = 0; qq < 4; qq++) {
            float m = s[qq];
#pragma unroll
            for (int o = 16; o; o >>= 1) m = fmaxf(m, __shfl_xor_sync(0xffffffffu, m, o));
            if (lane == 0) redm[qq * 8 + w] = m;
        }
        __syncthreads();
        float mq[4], denomq[4];
#pragma unroll
        for (int qq = 0; qq < 4; qq++) {
            float m = redm[qq * 8];
#pragma unroll
            for (int j = 1; j < 5; j++) m = fmaxf(m, redm[qq * 8 + j]);
            mq[qq] = fmaxf(m, sink);
        }
#pragma unroll
        for (int qq = 0; qq < 4; qq++) {
            float p = fexp(s[qq] - mq[qq]);
            sc[qq * 160 + tid] = p;
#pragma unroll
            for (int o = 16; o; o >>= 1) p += __shfl_xor_sync(0xffffffffu, p, o);
            if (lane == 0) reds[qq * 8 + w] = p;
        }
        __syncthreads();
#pragma unroll
        for (int qq = 0; qq < 4; qq++) {
            float sum = reds[qq * 8] + reds[qq * 8 + 1] + reds[qq * 8 + 2] +
                        reds[qq * 8 + 3] + reds[qq * 8 + 4];
            denomq[qq] = sum + fexp(sink - mq[qq]);
        }
        if (w < 4) {
            const int qg = q0 + w;
            int loG = qg - 127; if (loG < 0) loG = 0;
            const int lo = loG - kstartU, hi = qg - kstartU;
            float2 acc = {0.f, 0.f};
            const float* scw = sc + w * 160;
            const float* vb = vs + lane * 2;
            for (int j = lo; j <= hi; j++) {
                float p = scw[j];
                float2 v = *(const float2*)(vb + j * KV_PITCH);
                acc.x = fmaf(p, v.x, acc.x);
                acc.y = fmaf(p, v.y, acc.y);
            }
            float inv = 1.0f / denomq[w];
            int t = b * S_LEN + qg;
            int kcol = (kh * 8 + h8) * 64 + lane * 2;
            size_t o = offP(t, kcol, NKC_O);
            *(__half2*)(cpk + o) = __floats2half2_rn(acc.x * inv, acc.y * inv);
        }
        __syncthreads();
    }
}

// ---------------------------------------------------------------------------
// Launch
// ---------------------------------------------------------------------------
extern "C" void kernel_launch(void* const* d_in, const int* in_sizes, int n_in,
                              void* d_out, int out_size) {
    const float* x     = (const float*)d_in[0];
    const float* wq    = (const float*)d_in[1];
    const float* bq    = (const float*)d_in[2];
    const float* wk    = (const float*)d_in[3];
    const float* bk    = (const float*)d_in[4];
    const float* wv    = (const float*)d_in[5];
    const float* bv    = (const float*)d_in[6];
    const float* wo    = (const float*)d_in[7];
    const float* bo    = (const float*)d_in[8];
    const float* sinks = (const float*)d_in[9];
    const int* positions = (const int*)d_in[10];
    float* out = (float*)d_out;

    void *xpk, *wbh, *wobh, *cpk, *qkv, *biasqkv;
    cudaGetSymbolAddress(&xpk, g_xpk);
    cudaGetSymbolAddress(&wbh, g_wbh);
    cudaGetSymbolAddress(&wobh, g_wobh);
    cudaGetSymbolAddress(&cpk, g_cpk);
    cudaGetSymbolAddress(&qkv, g_qkv);
    cudaGetSymbolAddress(&biasqkv, g_biasqkv);

    float* qkvp = (float*)qkv;

    cudaFuncSetAttribute(gemm_tc, cudaFuncAttributeMaxDynamicSharedMemorySize, GEMM_SMEM);
    cudaFuncSetAttribute(attn_kernel, cudaFuncAttributeMaxDynamicSharedMemorySize, ATTN_SMEM);

    // 1. pack inputs/weights (single fp16 plane each)
    pack_x<<<dim3(12, T_TOK), 256>>>(x, (__half*)xpk);
    tsp1<<<dim3(128, 90), dim3(32, 8)>>>(wq, (__half*)wbh, D_DIM, NH, NKC_QKV, 0);
    tsp1<<<dim3(16, 90), dim3(32, 8)>>>(wk, (__half*)wbh, D_DIM, KVH, NKC_QKV, NH);
    tsp1<<<dim3(16, 90), dim3(32, 8)>>>(wv, (__half*)wbh, D_DIM, KVH, NKC_QKV, NH + KVH);
    tsp1<<<dim3(92, 128), dim3(32, 8)>>>(wo, (__half*)wobh, NH, D_DIM, NKC_O, 0);
    concat_bias<<<(QKV_COLS + 255) / 256, 256>>>(bq, bk, bv, (float*)biasqkv);

    // 2. fused QKV projection (single-term)
    gemm_tc<<<dim3(QKV_COLS / 128, T_TOK / 128), 256, GEMM_SMEM>>>(
        (const __half*)xpk, (const __half*)wbh,
        (const float*)biasqkv, qkvp, NKC_QKV, QKV_COLS, QKV_COLS);

    // 3. RoPE
    rope_kernel<<<T_TOK, 256>>>(qkvp, positions);

    // 4. attention (writes packed fp16 ctx)
    attn_kernel<<<dim3(S_LEN / 4, 8, B_BATCH), 160, ATTN_SMEM>>>(
        qkvp, sinks, (__half*)cpk);

    // 5. output projection (single-term)
    gemm_tc<<<dim3(OPAD / 128, T_TOK / 128), 256, GEMM_SMEM>>>(
        (const __half*)cpk, (const __half*)wobh,
        bo, out, NKC_O, D_DIM, D_DIM);
}

// round 8
// speedup vs baseline: 3.3912x; 1.0696x over previous
#include <cuda_runtime.h>
#include <cuda_fp16.h>
#include <cstdint>

// ---------------------------------------------------------------------------
// Problem constants
// ---------------------------------------------------------------------------
#define T_TOK   2048
#define D_DIM   2880
#define S_LEN   1024
#define B_BATCH 2
#define WIN     128
#define NH      4096
#define KVH     512
#define QKV_COLS 5120
#define OPAD    2944
#define NKC_QKV 90        // 2880/32
#define NKC_O   128       // 4096/32

// ---------------------------------------------------------------------------
// Scratch
// ---------------------------------------------------------------------------
__device__ __half g_xpk [(size_t)16 * NKC_QKV * 128 * 32];   // x packed fp16 (A blobs)
__device__ __half g_wbh [(size_t)40 * NKC_QKV * 128 * 32];   // qkv weights (B blobs)
__device__ __half g_wobh[(size_t)23 * NKC_O   * 128 * 32];   // wo (B blobs)
__device__ __half g_cpk [(size_t)16 * NKC_O   * 128 * 32];   // ctx packed fp16 (A blobs)
__device__ float  g_qkv [(size_t)T_TOK * QKV_COLS];
__device__ float  g_opart[(size_t)2 * T_TOK * OPAD];         // O split-K partials
__device__ float  g_biasqkv[QKV_COLS];

// ---------------------------------------------------------------------------
// Packed layout: 128-row x 32-k tiles, row = 64B, 16B chunks XOR-swizzled by
// ((row>>1)&3) so ldmatrix is conflict-free while bulk copies stay linear.
// ---------------------------------------------------------------------------
__device__ __forceinline__ size_t offP(int r_glob, int k, int nkc) {
    int r = r_glob & 127, ck = (k >> 3) & 3, w = k & 7;
    return ((((size_t)(r_glob >> 7)) * nkc + (k >> 5)) * 128 + r) * 32 +
           (((ck ^ ((r >> 1) & 3)) << 3) + w);
}

// ---------------------------------------------------------------------------
// PTX helpers
// ---------------------------------------------------------------------------
__device__ __forceinline__ void mbar_init(uint32_t a, uint32_t cnt) {
    asm volatile("mbarrier.init.shared.b64 [%0], %1;" :: "r"(a), "r"(cnt) : "memory");
}
__device__ __forceinline__ void mbar_wait(uint32_t a, int ph) {
    uint32_t done = 0;
    while (!done) {
        asm volatile("{\n\t.reg .pred p;\n\t"
                     "mbarrier.try_wait.parity.acquire.cta.shared::cta.b64 p, [%1], %2, 0x989680;\n\t"
                     "selp.b32 %0,1,0,p;\n\t}"
                     : "=r"(done) : "r"(a), "r"((uint32_t)ph) : "memory");
    }
}
__device__ __forceinline__ void expect_tx(uint32_t a, uint32_t bytes) {
    asm volatile("mbarrier.arrive.expect_tx.shared::cta.b64 _, [%0], %1;"
                 :: "r"(a), "r"(bytes) : "memory");
}
__device__ __forceinline__ void bulk_g2s(uint32_t sdst, const void* gsrc,
                                         uint32_t bytes, uint32_t mbar) {
    asm volatile("cp.async.bulk.shared::cluster.global.mbarrier::complete_tx::bytes "
                 "[%0], [%1], %2, [%3];"
                 :: "r"(sdst), "l"(__cvta_generic_to_global(gsrc)), "r"(bytes), "r"(mbar)
                 : "memory");
}
__device__ __forceinline__ void ldmx4(uint32_t* d, uint32_t addr) {
    asm volatile("ldmatrix.sync.aligned.m8n8.x4.shared.b16 {%0,%1,%2,%3}, [%4];"
                 : "=r"(d[0]), "=r"(d[1]), "=r"(d[2]), "=r"(d[3]) : "r"(addr));
}
__device__ __forceinline__ void mma16816(float* c, const uint32_t* a, const uint32_t* b) {
    asm volatile(
        "mma.sync.aligned.m16n8k16.row.col.f32.f16.f16.f32 "
        "{%0,%1,%2,%3},{%4,%5,%6,%7},{%8,%9},{%0,%1,%2,%3};\n"
        : "+f"(c[0]), "+f"(c[1]), "+f"(c[2]), "+f"(c[3])
        : "r"(a[0]), "r"(a[1]), "r"(a[2]), "r"(a[3]), "r"(b[0]), "r"(b[1]));
}

// fast exp on the FMA pipe (x <= 0 path), rel err ~1e-7
__device__ __forceinline__ float fexp(float x) {
    x = fmaxf(x, -87.0f);
    float y = x * 1.44269504f;
    float n = rintf(y);
    float f = y - n;
    float p = 1.33336498e-3f;
    p = fmaf(p, f, 9.61011233e-3f);
    p = fmaf(p, f, 5.55040755e-2f);
    p = fmaf(p, f, 2.40226507e-1f);
    p = fmaf(p, f, 6.93147182e-1f);
    p = fmaf(p, f, 1.0f);
    return p * __int_as_float(((int)n + 127) << 23);
}

// ---------------------------------------------------------------------------
// Prep kernels
// ---------------------------------------------------------------------------
__global__ void pack_x(const float* __restrict__ x, __half* __restrict__ o) {
    int k = blockIdx.x * 256 + threadIdx.x;
    int t = blockIdx.y;
    if (k < D_DIM)
        o[offP(t, k, NKC_QKV)] = __float2half_rn(x[(size_t)t * D_DIM + k]);
}

// transpose single-plane into packed B layout
__global__ void tsp1(const float* __restrict__ in, __half* __restrict__ oh,
                     int R, int C, int nkc, int nbase) {
    __shared__ float tb[32][33];
    int c0 = blockIdx.x * 32, r0 = blockIdx.y * 32;
    int tx = threadIdx.x, ty = threadIdx.y;
#pragma unroll
    for (int i = 0; i < 4; i++) {
        int r = r0 + ty + i * 8, c = c0 + tx;
        tb[ty + i * 8][tx] = (c < C) ? in[(size_t)r * C + c] : 0.0f;
    }
    __syncthreads();
#pragma unroll
    for (int i = 0; i < 4; i++) {
        int n = nbase + c0 + ty + i * 8, k = r0 + tx;
        oh[offP(n, k, nkc)] = __float2half_rn(tb[tx][ty + i * 8]);
    }
}

__global__ void concat_bias(const float* __restrict__ bq, const float* __restrict__ bk,
                            const float* __restrict__ bv, float* __restrict__ out) {
    int i = blockIdx.x * blockDim.x + threadIdx.x;
    if (i < QKV_COLS)
        out[i] = (i < NH) ? bq[i] : (i < NH + KVH ? bk[i - NH] : bv[i - NH - KVH]);
}

// combine O split-K partials + bias -> final output [T, 2880]
__global__ void combine_o(const float* __restrict__ part, const float* __restrict__ bo,
                          float* __restrict__ out) {
    const int t = blockIdx.x;
    const float* p0 = part + (size_t)t * OPAD;
    const float* p1 = part + (size_t)T_TOK * OPAD + (size_t)t * OPAD;
    float* o = out + (size_t)t * D_DIM;
    for (int c = threadIdx.x * 4; c < D_DIM; c += 256 * 4) {
        float4 a = *(const float4*)(p0 + c);
        float4 b = *(const float4*)(p1 + c);
        float4 bb = *(const float4*)(bo + c);
        float4 r;
        r.x = a.x + b.x + bb.x;
        r.y = a.y + b.y + bb.y;
        r.z = a.z + b.z + bb.z;
        r.w = a.w + b.w + bb.w;
        *(float4*)(o + c) = r;
    }
}

// ---------------------------------------------------------------------------
// GEMM: 128x128 CTA tile, 256 threads (8 warps of 64x32), 2 CTAs/SM,
// 4-stage cp.async.bulk pipeline (depth-3 prefetch), single fp16 term.
// Supports split-K via kbase/nkc_run; bias nullable.
// ---------------------------------------------------------------------------
#define STAGE_BYTES 16384
#define NSTAGE      4
#define GEMM_SMEM   (128 + NSTAGE * STAGE_BYTES)

__global__ __launch_bounds__(256, 2) void gemm_tc(
    const __half* __restrict__ Apk, const __half* __restrict__ Bhp,
    const float* __restrict__ bias, float* __restrict__ C,
    int nkc_total, int nkc_run, int kbase, int Nreal, int ldc)
{
    extern __shared__ __align__(128) uint8_t dsm[];
    const uint32_t base = (uint32_t)__cvta_generic_to_shared(dsm);
    const uint32_t mb = base;
    const uint32_t sdata = base + 128;

    const int tid = threadIdx.x, lane = tid & 31, warp = tid >> 5;
    const int wm = warp >> 2, wn = warp & 3;
    const int mt = blockIdx.y, nt = blockIdx.x;

    if (tid == 0)
#pragma unroll
        for (int s = 0; s < NSTAGE; s++) mbar_init(mb + s * 8, 1);
    __syncthreads();

    const __half* Asrc = Apk + (size_t)mt * nkc_total * 4096 + (size_t)kbase * 4096;
    const __half* Bsrc = Bhp + (size_t)nt * nkc_total * 4096 + (size_t)kbase * 4096;

    float c[4][4][4];
#pragma unroll
    for (int mi = 0; mi < 4; mi++)
#pragma unroll
        for (int ni = 0; ni < 4; ni++)
#pragma unroll
            for (int r = 0; r < 4; r++) c[mi][ni][r] = 0.0f;

    if (tid == 0) {
#pragma unroll
        for (int s = 0; s < 3; s++) {
            uint32_t sb = sdata + s * STAGE_BYTES;
            expect_tx(mb + s * 8, 16384u);
            bulk_g2s(sb,        Asrc + (size_t)s * 4096, 8192, mb + s * 8);
            bulk_g2s(sb + 8192, Bsrc + (size_t)s * 4096, 8192, mb + s * 8);
        }
    }

    const int rA_l = lane & 15;
    const int ckA_l = lane >> 4;
    const int rB_l = (lane & 7) + ((lane >> 4) << 3);
    const int ckB_l = (lane >> 3) & 1;

    for (int i = 0; i < nkc_run; i++) {
        const int s = i & (NSTAGE - 1);
        const int ph = (i >> 2) & 1;
        mbar_wait(mb + s * 8, ph);

        const uint32_t sA = sdata + s * STAGE_BYTES;
        const uint32_t sB = sA + 8192;

#pragma unroll
        for (int ks = 0; ks < 2; ks++) {
            uint32_t a[4][4];
#pragma unroll
            for (int mi = 0; mi < 4; mi++) {
                int r = wm * 64 + mi * 16 + rA_l;
                int ck = ks * 2 + ckA_l;
                ldmx4(a[mi], sA + r * 64 + ((ck ^ ((r >> 1) & 3)) << 4));
            }
            uint32_t b[4][2];
            {
                int ck = ks * 2 + ckB_l;
#pragma unroll
                for (int p = 0; p < 2; p++) {
                    int r = wn * 32 + p * 16 + rB_l;
                    uint32_t d[4];
                    ldmx4(d, sB + r * 64 + ((ck ^ ((r >> 1) & 3)) << 4));
                    b[p * 2][0] = d[0]; b[p * 2][1] = d[1];
                    b[p * 2 + 1][0] = d[2]; b[p * 2 + 1][1] = d[3];
                }
            }
#pragma unroll
            for (int mi = 0; mi < 4; mi++)
#pragma unroll
                for (int ni = 0; ni < 4; ni++) mma16816(c[mi][ni], a[mi], b[ni]);
        }
        __syncthreads();
        if (tid == 0 && i + 3 < nkc_run) {
            const int s2 = (i + 3) & (NSTAGE - 1);
            uint32_t sb = sdata + s2 * STAGE_BYTES;
            expect_tx(mb + s2 * 8, 16384u);
            bulk_g2s(sb,        Asrc + (size_t)(i + 3) * 4096, 8192, mb + s2 * 8);
            bulk_g2s(sb + 8192, Bsrc + (size_t)(i + 3) * 4096, 8192, mb + s2 * 8);
        }
    }

#pragma unroll
    for (int mi = 0; mi < 4; mi++) {
        int row = mt * 128 + wm * 64 + mi * 16 + (lane >> 2);
#pragma unroll
        for (int ni = 0; ni < 4; ni++) {
            int col = nt * 128 + wn * 32 + ni * 8 + (lane & 3) * 2;
            if (col < Nreal) {
                float2 bb = bias ? *(const float2*)(bias + col) : make_float2(0.f, 0.f);
                float2 v0 = {c[mi][ni][0] + bb.x, c[mi][ni][1] + bb.y};
                float2 v1 = {c[mi][ni][2] + bb.x, c[mi][ni][3] + bb.y};
                *(float2*)(C + (size_t)row * ldc + col) = v0;
                *(float2*)(C + (size_t)(row + 8) * ldc + col) = v1;
            }
        }
    }
}

// ---------------------------------------------------------------------------
// RoPE (in place on q heads 0..63 + k heads 64..71)
// ---------------------------------------------------------------------------
__global__ void rope_kernel(float* __restrict__ qkv, const int* __restrict__ positions) {
    __shared__ float cs[32], sn[32];
    const int t = blockIdx.x;
    const int pos = positions[t] % S_LEN;
    if (threadIdx.x < 32) {
        int i = threadIdx.x;
        float freq   = powf(150000.0f, (float)i / 32.0f);
        float interp = 1.0f / (32.0f * freq);
        float extrap = 1.0f / freq;
        float lnT    = logf(150000.0f);
        float low    = 32.0f * logf(4096.0f / (32.0f * 6.2831853071795864f)) / lnT;
        float high   = 32.0f * logf(4096.0f / 6.2831853071795864f) / lnT;
        float ramp   = fminf(fmaxf(((float)i - low) / (high - low), 0.0f), 1.0f);
        float inv    = interp * ramp + extrap * (1.0f - ramp);
        float conc   = 0.1f * logf(32.0f) + 1.0f;
        float tt     = (float)pos * inv;
        cs[i] = cosf(tt) * conc;
        sn[i] = sinf(tt) * conc;
    }
    __syncthreads();
    for (int idx = threadIdx.x; idx < 72 * 32; idx += blockDim.x) {
        int head = idx >> 5;
        int i = idx & 31;
        float* base = qkv + (size_t)t * QKV_COLS + head * 64;
        float x1 = base[i], x2 = base[i + 32];
        base[i]      = x1 * cs[i] - x2 * sn[i];
        base[i + 32] = x2 * cs[i] + x1 * sn[i];
    }
}

// ---------------------------------------------------------------------------
// Attention: 4 queries x 1 kv-head per block, 160 threads, K direct to regs
// (no K smem) -> ~45.6KB smem, 3 blocks/SM (reg-limited).
// V region padded to 8648 floats so qsm stays 16B-aligned (float4 reads).
// ---------------------------------------------------------------------------
#define KV_PITCH 66
#define VS_FLOATS 8648    // 131*66 = 8646, padded to multiple of 4
#define ATTN_SMEM ((VS_FLOATS + 2048 + 4 * 160 + 64) * 4)

__global__ __launch_bounds__(160, 3) void attn_kernel(
    const float* __restrict__ qkv, const float* __restrict__ sinks,
    __half* __restrict__ cpk)
{
    extern __shared__ float sm[];
    float* vs   = sm;                          // 131*66 (padded to 8648)
    float* qsm  = vs + VS_FLOATS;              // 2048, 16B-aligned
    float* sc   = qsm + 2048;                  // 4*160
    float* redm = sc + 4 * 160;                // 32
    float* reds = redm + 32;                   // 32

    const int q0  = blockIdx.x * 4;
    const int kh  = blockIdx.y;
    const int b   = blockIdx.z;
    const int tid = threadIdx.x;
    const int lane = tid & 31, w = tid >> 5;
    const int kstartU = (q0 >= 127) ? q0 - 127 : 0;
    const int cntU = q0 + 3 - kstartU + 1;

    // stage Q (float4-packed over qq) and V window
    for (int i = tid; i < 2048; i += 160) {
        int qq = i >> 9, r = i & 511;
        qsm[r * 4 + qq] = qkv[(size_t)(b * S_LEN + q0 + qq) * QKV_COLS + kh * 512 + r];
    }
    for (int i = tid; i < cntU * 64; i += 160) {
        int r = i >> 6, d = i & 63;
        size_t rb = (size_t)(b * S_LEN + kstartU + r) * QKV_COLS;
        vs[r * KV_PITCH + d] = qkv[rb + 4608 + kh * 64 + d];
    }

    // K row for this thread straight from gmem into registers
    const bool havek = tid < cntU;
    float kreg[64];
    if (havek) {
        const float4* kp = (const float4*)(qkv +
            (size_t)(b * S_LEN + kstartU + tid) * QKV_COLS + 4096 + kh * 64);
#pragma unroll
        for (int u = 0; u < 16; u++) {
            float4 v = kp[u];
            kreg[u * 4 + 0] = v.x; kreg[u * 4 + 1] = v.y;
            kreg[u * 4 + 2] = v.z; kreg[u * 4 + 3] = v.w;
        }
    } else {
#pragma unroll
        for (int d = 0; d < 64; d++) kreg[d] = 0.0f;
    }
    __syncthreads();

    const int kpos = kstartU + tid;

    for (int h8 = 0; h8 < 8; h8++) {
        const float sink = sinks[kh * 8 + h8];
        float s[4] = {-1e30f, -1e30f, -1e30f, -1e30f};
        if (havek) {
            float a0 = 0.f, a1 = 0.f, a2 = 0.f, a3 = 0.f;
            const float4* qp = (const float4*)(qsm + h8 * 256);
#pragma unroll
            for (int d = 0; d < 64; d++) {
                float4 qv = qp[d];
                float kd = kreg[d];
                a0 = fmaf(kd, qv.x, a0);
                a1 = fmaf(kd, qv.y, a1);
                a2 = fmaf(kd, qv.z, a2);
                a3 = fmaf(kd, qv.w, a3);
            }
            float aa[4] = {a0, a1, a2, a3};
#pragma unroll
            for (int qq = 0; qq < 4; qq++) {
                int qg = q0 + qq;
                int loG = qg - 127; if (loG < 0) loG = 0;
                s[qq] = (kpos >= loG && kpos <= qg) ? aa[qq] * 0.125f : -1e30f;
            }
        }
#pragma unroll
        for (int qq = 0; qq < 4; qq++) {
            float m = s[qq];
#pragma unroll
            for (int o = 16; o; o >>= 1) m = fmaxf(m, __shfl_xor_sync(0xffffffffu, m, o));
            if (lane == 0) redm[qq * 8 + w] = m;
        }
        __syncthreads();
        float mq[4], denomq[4];
#pragma unroll
        for (int qq = 0; qq < 4; qq++) {
            float m = redm[qq * 8];
#pragma unroll
            for (int j = 1; j < 5; j++) m = fmaxf(m, redm[qq * 8 + j]);
            mq[qq] = fmaxf(m, sink);
        }
#pragma unroll
        for (int qq = 0; qq < 4; qq++) {
            float p = fexp(s[qq] - mq[qq]);
            sc[qq * 160 + tid] = p;
#pragma unroll
            for (int o = 16; o; o >>= 1) p += __shfl_xor_sync(0xffffffffu, p, o);
            if (lane == 0) reds[qq * 8 + w] = p;
        }
        __syncthreads();
#pragma unroll
        for (int qq = 0; qq < 4; qq++) {
            float sum = reds[qq * 8] + reds[qq * 8 + 1] + reds[qq * 8 + 2] +
                        reds[qq * 8 + 3] + reds[qq * 8 + 4];
            denomq[qq] = sum + fexp(sink - mq[qq]);
        }
        if (w < 4) {
            const int qg = q0 + w;
            int loG = qg - 127; if (loG < 0) loG = 0;
            const int lo = loG - kstartU, hi = qg - kstartU;
            float2 acc = {0.f, 0.f};
            const float* scw = sc + w * 160;
            const float* vb = vs + lane * 2;
            for (int j = lo; j <= hi; j++) {
                float p = scw[j];
                float2 v = *(const float2*)(vb + j * KV_PITCH);
                acc.x = fmaf(p, v.x, acc.x);
                acc.y = fmaf(p, v.y, acc.y);
            }
            float inv = 1.0f / denomq[w];
            int t = b * S_LEN + qg;
            int kcol = (kh * 8 + h8) * 64 + lane * 2;
            size_t o = offP(t, kcol, NKC_O);
            *(__half2*)(cpk + o) = __floats2half2_rn(acc.x * inv, acc.y * inv);
        }
        __syncthreads();
    }
}

// ---------------------------------------------------------------------------
// Launch
// ---------------------------------------------------------------------------
extern "C" void kernel_launch(void* const* d_in, const int* in_sizes, int n_in,
                              void* d_out, int out_size) {
    const float* x     = (const float*)d_in[0];
    const float* wq    = (const float*)d_in[1];
    const float* bq    = (const float*)d_in[2];
    const float* wk    = (const float*)d_in[3];
    const float* bk    = (const float*)d_in[4];
    const float* wv    = (const float*)d_in[5];
    const float* bv    = (const float*)d_in[6];
    const float* wo    = (const float*)d_in[7];
    const float* bo    = (const float*)d_in[8];
    const float* sinks = (const float*)d_in[9];
    const int* positions = (const int*)d_in[10];
    float* out = (float*)d_out;

    void *xpk, *wbh, *wobh, *cpk, *qkv, *opart, *biasqkv;
    cudaGetSymbolAddress(&xpk, g_xpk);
    cudaGetSymbolAddress(&wbh, g_wbh);
    cudaGetSymbolAddress(&wobh, g_wobh);
    cudaGetSymbolAddress(&cpk, g_cpk);
    cudaGetSymbolAddress(&qkv, g_qkv);
    cudaGetSymbolAddress(&opart, g_opart);
    cudaGetSymbolAddress(&biasqkv, g_biasqkv);

    float* qkvp = (float*)qkv;
    float* opartp = (float*)opart;

    cudaFuncSetAttribute(gemm_tc, cudaFuncAttributeMaxDynamicSharedMemorySize, GEMM_SMEM);
    cudaFuncSetAttribute(attn_kernel, cudaFuncAttributeMaxDynamicSharedMemorySize, ATTN_SMEM);

    // 1. pack inputs/weights (single fp16 plane each)
    pack_x<<<dim3(12, T_TOK), 256>>>(x, (__half*)xpk);
    tsp1<<<dim3(128, 90), dim3(32, 8)>>>(wq, (__half*)wbh, D_DIM, NH, NKC_QKV, 0);
    tsp1<<<dim3(16, 90), dim3(32, 8)>>>(wk, (__half*)wbh, D_DIM, KVH, NKC_QKV, NH);
    tsp1<<<dim3(16, 90), dim3(32, 8)>>>(wv, (__half*)wbh, D_DIM, KVH, NKC_QKV, NH + KVH);
    tsp1<<<dim3(92, 128), dim3(32, 8)>>>(wo, (__half*)wobh, NH, D_DIM, NKC_O, 0);
    concat_bias<<<(QKV_COLS + 255) / 256, 256>>>(bq, bk, bv, (float*)biasqkv);

    // 2. fused QKV projection (single-term, full-K)
    gemm_tc<<<dim3(QKV_COLS / 128, T_TOK / 128), 256, GEMM_SMEM>>>(
        (const __half*)xpk, (const __half*)wbh,
        (const float*)biasqkv, qkvp, NKC_QKV, NKC_QKV, 0, QKV_COLS, QKV_COLS);

    // 3. RoPE
    rope_kernel<<<T_TOK, 256>>>(qkvp, positions);

    // 4. attention (writes packed fp16 ctx)
    attn_kernel<<<dim3(S_LEN / 4, 8, B_BATCH), 160, ATTN_SMEM>>>(
        qkvp, sinks, (__half*)cpk);

    // 5. output projection: split-K=2 into partials, then combine (+bias)
    gemm_tc<<<dim3(OPAD / 128, T_TOK / 128), 256, GEMM_SMEM>>>(
        (const __half*)cpk, (const __half*)wobh,
        (const float*)nullptr, opartp, NKC_O, 64, 0, OPAD, OPAD);
    gemm_tc<<<dim3(OPAD / 128, T_TOK / 128), 256, GEMM_SMEM>>>(
        (const __half*)cpk, (const __half*)wobh,
        (const float*)nullptr, opartp + (size_t)T_TOK * OPAD, NKC_O, 64, 64, OPAD, OPAD);
    combine_o<<<T_TOK, 256>>>(opartp, bo, out);
}

// round 9
// speedup vs baseline: 3.5183x; 1.0375x over previous
#include <cuda_runtime.h>
#include <cuda_fp16.h>
#include <cstdint>

// ---------------------------------------------------------------------------
// Problem constants
// ---------------------------------------------------------------------------
#define T_TOK   2048
#define D_DIM   2880
#define S_LEN   1024
#define B_BATCH 2
#define WIN     128
#define NH      4096
#define KVH     512
#define QKV_COLS 5120
#define OPAD    2944
#define NKC_QKV 90        // 2880/32
#define NKC_O   128       // 4096/32

// ---------------------------------------------------------------------------
// Scratch
// ---------------------------------------------------------------------------
__device__ __half g_xpk [(size_t)16 * NKC_QKV * 128 * 32];   // x packed fp16 (A blobs)
__device__ __half g_wbh [(size_t)40 * NKC_QKV * 128 * 32];   // qkv weights (B blobs)
__device__ __half g_wobh[(size_t)23 * NKC_O   * 128 * 32];   // wo (B blobs)
__device__ __half g_cpk [(size_t)16 * NKC_O   * 128 * 32];   // ctx packed fp16 (A blobs)
__device__ float  g_qkv  [(size_t)T_TOK * QKV_COLS];
__device__ float  g_qkvp [(size_t)2 * T_TOK * QKV_COLS];     // QKV split-K partials
__device__ float  g_opart[(size_t)2 * T_TOK * OPAD];         // O split-K partials
__device__ float  g_biasqkv[QKV_COLS];

// ---------------------------------------------------------------------------
// Packed layout: 128-row x 32-k tiles, row = 64B, 16B chunks XOR-swizzled by
// ((row>>1)&3) so ldmatrix is conflict-free while bulk copies stay linear.
// ---------------------------------------------------------------------------
__device__ __forceinline__ size_t offP(int r_glob, int k, int nkc) {
    int r = r_glob & 127, ck = (k >> 3) & 3, w = k & 7;
    return ((((size_t)(r_glob >> 7)) * nkc + (k >> 5)) * 128 + r) * 32 +
           (((ck ^ ((r >> 1) & 3)) << 3) + w);
}

// ---------------------------------------------------------------------------
// PTX helpers
// ---------------------------------------------------------------------------
__device__ __forceinline__ void mbar_init(uint32_t a, uint32_t cnt) {
    asm volatile("mbarrier.init.shared.b64 [%0], %1;" :: "r"(a), "r"(cnt) : "memory");
}
__device__ __forceinline__ void mbar_wait(uint32_t a, int ph) {
    uint32_t done = 0;
    while (!done) {
        asm volatile("{\n\t.reg .pred p;\n\t"
                     "mbarrier.try_wait.parity.acquire.cta.shared::cta.b64 p, [%1], %2, 0x989680;\n\t"
                     "selp.b32 %0,1,0,p;\n\t}"
                     : "=r"(done) : "r"(a), "r"((uint32_t)ph) : "memory");
    }
}
__device__ __forceinline__ void expect_tx(uint32_t a, uint32_t bytes) {
    asm volatile("mbarrier.arrive.expect_tx.shared::cta.b64 _, [%0], %1;"
                 :: "r"(a), "r"(bytes) : "memory");
}
__device__ __forceinline__ void bulk_g2s(uint32_t sdst, const void* gsrc,
                                         uint32_t bytes, uint32_t mbar) {
    asm volatile("cp.async.bulk.shared::cluster.global.mbarrier::complete_tx::bytes "
                 "[%0], [%1], %2, [%3];"
                 :: "r"(sdst), "l"(__cvta_generic_to_global(gsrc)), "r"(bytes), "r"(mbar)
                 : "memory");
}
__device__ __forceinline__ void ldmx4(uint32_t* d, uint32_t addr) {
    asm volatile("ldmatrix.sync.aligned.m8n8.x4.shared.b16 {%0,%1,%2,%3}, [%4];"
                 : "=r"(d[0]), "=r"(d[1]), "=r"(d[2]), "=r"(d[3]) : "r"(addr));
}
__device__ __forceinline__ void mma16816(float* c, const uint32_t* a, const uint32_t* b) {
    asm volatile(
        "mma.sync.aligned.m16n8k16.row.col.f32.f16.f16.f32 "
        "{%0,%1,%2,%3},{%4,%5,%6,%7},{%8,%9},{%0,%1,%2,%3};\n"
        : "+f"(c[0]), "+f"(c[1]), "+f"(c[2]), "+f"(c[3])
        : "r"(a[0]), "r"(a[1]), "r"(a[2]), "r"(a[3]), "r"(b[0]), "r"(b[1]));
}

// fast exp on the FMA pipe (x <= 0 path), rel err ~1e-7
__device__ __forceinline__ float fexp(float x) {
    x = fmaxf(x, -87.0f);
    float y = x * 1.44269504f;
    float n = rintf(y);
    float f = y - n;
    float p = 1.33336498e-3f;
    p = fmaf(p, f, 9.61011233e-3f);
    p = fmaf(p, f, 5.55040755e-2f);
    p = fmaf(p, f, 2.40226507e-1f);
    p = fmaf(p, f, 6.93147182e-1f);
    p = fmaf(p, f, 1.0f);
    return p * __int_as_float(((int)n + 127) << 23);
}

// ---------------------------------------------------------------------------
// Prep kernels
// ---------------------------------------------------------------------------
__global__ void pack_x(const float* __restrict__ x, __half* __restrict__ o) {
    int k = blockIdx.x * 256 + threadIdx.x;
    int t = blockIdx.y;
    if (k < D_DIM)
        o[offP(t, k, NKC_QKV)] = __float2half_rn(x[(size_t)t * D_DIM + k]);
}

// transpose single-plane into packed B layout
__global__ void tsp1(const float* __restrict__ in, __half* __restrict__ oh,
                     int R, int C, int nkc, int nbase) {
    __shared__ float tb[32][33];
    int c0 = blockIdx.x * 32, r0 = blockIdx.y * 32;
    int tx = threadIdx.x, ty = threadIdx.y;
#pragma unroll
    for (int i = 0; i < 4; i++) {
        int r = r0 + ty + i * 8, c = c0 + tx;
        tb[ty + i * 8][tx] = (c < C) ? in[(size_t)r * C + c] : 0.0f;
    }
    __syncthreads();
#pragma unroll
    for (int i = 0; i < 4; i++) {
        int n = nbase + c0 + ty + i * 8, k = r0 + tx;
        oh[offP(n, k, nkc)] = __float2half_rn(tb[tx][ty + i * 8]);
    }
}

__global__ void concat_bias(const float* __restrict__ bq, const float* __restrict__ bk,
                            const float* __restrict__ bv, float* __restrict__ out) {
    int i = blockIdx.x * blockDim.x + threadIdx.x;
    if (i < QKV_COLS)
        out[i] = (i < NH) ? bq[i] : (i < NH + KVH ? bk[i - NH] : bv[i - NH - KVH]);
}

// ---------------------------------------------------------------------------
// Fused: combine QKV split-K partials + bias + RoPE -> qkv buffer
// ---------------------------------------------------------------------------
__global__ __launch_bounds__(256) void combine_qkv_rope(
    const float* __restrict__ part, const float* __restrict__ bias,
    const int* __restrict__ positions, float* __restrict__ qkv)
{
    __shared__ float row[QKV_COLS];
    __shared__ float cs[32], sn[32];
    const int t = blockIdx.x;
    const int tid = threadIdx.x;

    if (tid < 32) {
        int i = tid;
        int pos = positions[t] % S_LEN;
        float freq   = powf(150000.0f, (float)i / 32.0f);
        float interp = 1.0f / (32.0f * freq);
        float extrap = 1.0f / freq;
        float lnT    = logf(150000.0f);
        float low    = 32.0f * logf(4096.0f / (32.0f * 6.2831853071795864f)) / lnT;
        float high   = 32.0f * logf(4096.0f / 6.2831853071795864f) / lnT;
        float ramp   = fminf(fmaxf(((float)i - low) / (high - low), 0.0f), 1.0f);
        float inv    = interp * ramp + extrap * (1.0f - ramp);
        float conc   = 0.1f * logf(32.0f) + 1.0f;
        float tt     = (float)pos * inv;
        cs[i] = cosf(tt) * conc;
        sn[i] = sinf(tt) * conc;
    }

    const float* p0 = part + (size_t)t * QKV_COLS;
    const float* p1 = part + (size_t)T_TOK * QKV_COLS + (size_t)t * QKV_COLS;
    float* orow = qkv + (size_t)t * QKV_COLS;

    for (int c = tid * 4; c < QKV_COLS; c += 256 * 4) {
        float4 a = *(const float4*)(p0 + c);
        float4 b = *(const float4*)(p1 + c);
        float4 bb = *(const float4*)(bias + c);
        float4 r;
        r.x = a.x + b.x + bb.x;
        r.y = a.y + b.y + bb.y;
        r.z = a.z + b.z + bb.z;
        r.w = a.w + b.w + bb.w;
        if (c >= NH + KVH) {            // V columns: no rope, write directly
            *(float4*)(orow + c) = r;
        } else {
            *(float4*)(row + c) = r;
        }
    }
    __syncthreads();

    // rope on q (heads 0..63) + k (heads 64..71): 72 heads x 32 rotations
    for (int idx = tid; idx < 72 * 32; idx += 256) {
        int head = idx >> 5, i = idx & 31;
        float x1 = row[head * 64 + i], x2 = row[head * 64 + i + 32];
        orow[head * 64 + i]      = x1 * cs[i] - x2 * sn[i];
        orow[head * 64 + i + 32] = x2 * cs[i] + x1 * sn[i];
    }
}

// combine O split-K partials + bias -> final output [T, 2880]
__global__ void combine_o(const float* __restrict__ part, const float* __restrict__ bo,
                          float* __restrict__ out) {
    const int t = blockIdx.x;
    const float* p0 = part + (size_t)t * OPAD;
    const float* p1 = part + (size_t)T_TOK * OPAD + (size_t)t * OPAD;
    float* o = out + (size_t)t * D_DIM;
    for (int c = threadIdx.x * 4; c < D_DIM; c += 256 * 4) {
        float4 a = *(const float4*)(p0 + c);
        float4 b = *(const float4*)(p1 + c);
        float4 bb = *(const float4*)(bo + c);
        float4 r;
        r.x = a.x + b.x + bb.x;
        r.y = a.y + b.y + bb.y;
        r.z = a.z + b.z + bb.z;
        r.w = a.w + b.w + bb.w;
        *(float4*)(o + c) = r;
    }
}

// ---------------------------------------------------------------------------
// GEMM: 128x128 CTA tile, 256 threads (8 warps of 64x32), 2 CTAs/SM,
// 4-stage cp.async.bulk pipeline (depth-3 prefetch), single fp16 term.
// grid.z = split-K slice: kbase = z*nkc_run, C += z*plane_stride.
// ---------------------------------------------------------------------------
#define STAGE_BYTES 16384
#define NSTAGE      4
#define GEMM_SMEM   (128 + NSTAGE * STAGE_BYTES)

__global__ __launch_bounds__(256, 2) void gemm_tc(
    const __half* __restrict__ Apk, const __half* __restrict__ Bhp,
    float* __restrict__ C,
    int nkc_total, int nkc_run, int Nreal, int ldc, size_t plane_stride)
{
    extern __shared__ __align__(128) uint8_t dsm[];
    const uint32_t base = (uint32_t)__cvta_generic_to_shared(dsm);
    const uint32_t mb = base;
    const uint32_t sdata = base + 128;

    const int tid = threadIdx.x, lane = tid & 31, warp = tid >> 5;
    const int wm = warp >> 2, wn = warp & 3;
    const int mt = blockIdx.y, nt = blockIdx.x;
    const int kbase = blockIdx.z * nkc_run;
    C += (size_t)blockIdx.z * plane_stride;

    if (tid == 0)
#pragma unroll
        for (int s = 0; s < NSTAGE; s++) mbar_init(mb + s * 8, 1);
    __syncthreads();

    const __half* Asrc = Apk + (size_t)mt * nkc_total * 4096 + (size_t)kbase * 4096;
    const __half* Bsrc = Bhp + (size_t)nt * nkc_total * 4096 + (size_t)kbase * 4096;

    float c[4][4][4];
#pragma unroll
    for (int mi = 0; mi < 4; mi++)
#pragma unroll
        for (int ni = 0; ni < 4; ni++)
#pragma unroll
            for (int r = 0; r < 4; r++) c[mi][ni][r] = 0.0f;

    if (tid == 0) {
#pragma unroll
        for (int s = 0; s < 3; s++) {
            uint32_t sb = sdata + s * STAGE_BYTES;
            expect_tx(mb + s * 8, 16384u);
            bulk_g2s(sb,        Asrc + (size_t)s * 4096, 8192, mb + s * 8);
            bulk_g2s(sb + 8192, Bsrc + (size_t)s * 4096, 8192, mb + s * 8);
        }
    }

    const int rA_l = lane & 15;
    const int ckA_l = lane >> 4;
    const int rB_l = (lane & 7) + ((lane >> 4) << 3);
    const int ckB_l = (lane >> 3) & 1;

    for (int i = 0; i < nkc_run; i++) {
        const int s = i & (NSTAGE - 1);
        const int ph = (i >> 2) & 1;
        mbar_wait(mb + s * 8, ph);

        const uint32_t sA = sdata + s * STAGE_BYTES;
        const uint32_t sB = sA + 8192;

#pragma unroll
        for (int ks = 0; ks < 2; ks++) {
            uint32_t a[4][4];
#pragma unroll
            for (int mi = 0; mi < 4; mi++) {
                int r = wm * 64 + mi * 16 + rA_l;
                int ck = ks * 2 + ckA_l;
                ldmx4(a[mi], sA + r * 64 + ((ck ^ ((r >> 1) & 3)) << 4));
            }
            uint32_t b[4][2];
            {
                int ck = ks * 2 + ckB_l;
#pragma unroll
                for (int p = 0; p < 2; p++) {
                    int r = wn * 32 + p * 16 + rB_l;
                    uint32_t d[4];
                    ldmx4(d, sB + r * 64 + ((ck ^ ((r >> 1) & 3)) << 4));
                    b[p * 2][0] = d[0]; b[p * 2][1] = d[1];
                    b[p * 2 + 1][0] = d[2]; b[p * 2 + 1][1] = d[3];
                }
            }
#pragma unroll
            for (int mi = 0; mi < 4; mi++)
#pragma unroll
                for (int ni = 0; ni < 4; ni++) mma16816(c[mi][ni], a[mi], b[ni]);
        }
        __syncthreads();
        if (tid == 0 && i + 3 < nkc_run) {
            const int s2 = (i + 3) & (NSTAGE - 1);
            uint32_t sb = sdata + s2 * STAGE_BYTES;
            expect_tx(mb + s2 * 8, 16384u);
            bulk_g2s(sb,        Asrc + (size_t)(i + 3) * 4096, 8192, mb + s2 * 8);
            bulk_g2s(sb + 8192, Bsrc + (size_t)(i + 3) * 4096, 8192, mb + s2 * 8);
        }
    }

#pragma unroll
    for (int mi = 0; mi < 4; mi++) {
        int row = mt * 128 + wm * 64 + mi * 16 + (lane >> 2);
#pragma unroll
        for (int ni = 0; ni < 4; ni++) {
            int col = nt * 128 + wn * 32 + ni * 8 + (lane & 3) * 2;
            if (col < Nreal) {
                float2 v0 = {c[mi][ni][0], c[mi][ni][1]};
                float2 v1 = {c[mi][ni][2], c[mi][ni][3]};
                *(float2*)(C + (size_t)row * ldc + col) = v0;
                *(float2*)(C + (size_t)(row + 8) * ldc + col) = v1;
            }
        }
    }
}

// ---------------------------------------------------------------------------
// Attention: 4 queries x 1 kv-head per block, 160 threads, K direct to regs
// (no K smem) -> ~45.6KB smem, 3 blocks/SM (reg-limited).
// ---------------------------------------------------------------------------
#define KV_PITCH 66
#define VS_FLOATS 8648    // 131*66 = 8646, padded to multiple of 4
#define ATTN_SMEM ((VS_FLOATS + 2048 + 4 * 160 + 64) * 4)

__global__ __launch_bounds__(160, 3) void attn_kernel(
    const float* __restrict__ qkv, const float* __restrict__ sinks,
    __half* __restrict__ cpk)
{
    extern __shared__ float sm[];
    float* vs   = sm;                          // 131*66 (padded to 8648)
    float* qsm  = vs + VS_FLOATS;              // 2048, 16B-aligned
    float* sc   = qsm + 2048;                  // 4*160
    float* redm = sc + 4 * 160;                // 32
    float* reds = redm + 32;                   // 32

    const int q0  = blockIdx.x * 4;
    const int kh  = blockIdx.y;
    const int b   = blockIdx.z;
    const int tid = threadIdx.x;
    const int lane = tid & 31, w = tid >> 5;
    const int kstartU = (q0 >= 127) ? q0 - 127 : 0;
    const int cntU = q0 + 3 - kstartU + 1;

    for (int i = tid; i < 2048; i += 160) {
        int qq = i >> 9, r = i & 511;
        qsm[r * 4 + qq] = qkv[(size_t)(b * S_LEN + q0 + qq) * QKV_COLS + kh * 512 + r];
    }
    for (int i = tid; i < cntU * 64; i += 160) {
        int r = i >> 6, d = i & 63;
        size_t rb = (size_t)(b * S_LEN + kstartU + r) * QKV_COLS;
        vs[r * KV_PITCH + d] = qkv[rb + 4608 + kh * 64 + d];
    }

    const bool havek = tid < cntU;
    float kreg[64];
    if (havek) {
        const float4* kp = (const float4*)(qkv +
            (size_t)(b * S_LEN + kstartU + tid) * QKV_COLS + 4096 + kh * 64);
#pragma unroll
        for (int u = 0; u < 16; u++) {
            float4 v = kp[u];
            kreg[u * 4 + 0] = v.x; kreg[u * 4 + 1] = v.y;
            kreg[u * 4 + 2] = v.z; kreg[u * 4 + 3] = v.w;
        }
    } else {
#pragma unroll
        for (int d = 0; d < 64; d++) kreg[d] = 0.0f;
    }
    __syncthreads();

    const int kpos = kstartU + tid;

    for (int h8 = 0; h8 < 8; h8++) {
        const float sink = sinks[kh * 8 + h8];
        float s[4] = {-1e30f, -1e30f, -1e30f, -1e30f};
        if (havek) {
            float a0 = 0.f, a1 = 0.f, a2 = 0.f, a3 = 0.f;
            const float4* qp = (const float4*)(qsm + h8 * 256);
#pragma unroll
            for (int d = 0; d < 64; d++) {
                float4 qv = qp[d];
                float kd = kreg[d];
                a0 = fmaf(kd, qv.x, a0);
                a1 = fmaf(kd, qv.y, a1);
                a2 = fmaf(kd, qv.z, a2);
                a3 = fmaf(kd, qv.w, a3);
            }
            float aa[4] = {a0, a1, a2, a3};
#pragma unroll
            for (int qq = 0; qq < 4; qq++) {
                int qg = q0 + qq;
                int loG = qg - 127; if (loG < 0) loG = 0;
                s[qq] = (kpos >= loG && kpos <= qg) ? aa[qq] * 0.125f : -1e30f;
            }
        }
#pragma unroll
        for (int qq = 0; qq < 4; qq++) {
            float m = s[qq];
#pragma unroll
            for (int o = 16; o; o >>= 1) m = fmaxf(m, __shfl_xor_sync(0xffffffffu, m, o));
            if (lane == 0) redm[qq * 8 + w] = m;
        }
        __syncthreads();
        float mq[4], denomq[4];
#pragma unroll
        for (int qq = 0; qq < 4; qq++) {
            float m = redm[qq * 8];
#pragma unroll
            for (int j = 1; j < 5; j++) m = fmaxf(m, redm[qq * 8 + j]);
            mq[qq] = fmaxf(m, sink);
        }
#pragma unroll
        for (int qq = 0; qq < 4; qq++) {
            float p = fexp(s[qq] - mq[qq]);
            sc[qq * 160 + tid] = p;
#pragma unroll
            for (int o = 16; o; o >>= 1) p += __shfl_xor_sync(0xffffffffu, p, o);
            if (lane == 0) reds[qq * 8 + w] = p;
        }
        __syncthreads();
#pragma unroll
        for (int qq = 0; qq < 4; qq++) {
            float sum = reds[qq * 8] + reds[qq * 8 + 1] + reds[qq * 8 + 2] +
                        reds[qq * 8 + 3] + reds[qq * 8 + 4];
            denomq[qq] = sum + fexp(sink - mq[qq]);
        }
        if (w < 4) {
            const int qg = q0 + w;
            int loG = qg - 127; if (loG < 0) loG = 0;
            const int lo = loG - kstartU, hi = qg - kstartU;
            float2 acc = {0.f, 0.f};
            const float* scw = sc + w * 160;
            const float* vb = vs + lane * 2;
            for (int j = lo; j <= hi; j++) {
                float p = scw[j];
                float2 v = *(const float2*)(vb + j * KV_PITCH);
                acc.x = fmaf(p, v.x, acc.x);
                acc.y = fmaf(p, v.y, acc.y);
            }
            float inv = 1.0f / denomq[w];
            int t = b * S_LEN + qg;
            int kcol = (kh * 8 + h8) * 64 + lane * 2;
            size_t o = offP(t, kcol, NKC_O);
            *(__half2*)(cpk + o) = __floats2half2_rn(acc.x * inv, acc.y * inv);
        }
        __syncthreads();
    }
}

// ---------------------------------------------------------------------------
// Launch
// ---------------------------------------------------------------------------
extern "C" void kernel_launch(void* const* d_in, const int* in_sizes, int n_in,
                              void* d_out, int out_size) {
    const float* x     = (const float*)d_in[0];
    const float* wq    = (const float*)d_in[1];
    const float* bq    = (const float*)d_in[2];
    const float* wk    = (const float*)d_in[3];
    const float* bk    = (const float*)d_in[4];
    const float* wv    = (const float*)d_in[5];
    const float* bv    = (const float*)d_in[6];
    const float* wo    = (const float*)d_in[7];
    const float* bo    = (const float*)d_in[8];
    const float* sinks = (const float*)d_in[9];
    const int* positions = (const int*)d_in[10];
    float* out = (float*)d_out;

    void *xpk, *wbh, *wobh, *cpk, *qkv, *qkvp_part, *opart, *biasqkv;
    cudaGetSymbolAddress(&xpk, g_xpk);
    cudaGetSymbolAddress(&wbh, g_wbh);
    cudaGetSymbolAddress(&wobh, g_wobh);
    cudaGetSymbolAddress(&cpk, g_cpk);
    cudaGetSymbolAddress(&qkv, g_qkv);
    cudaGetSymbolAddress(&qkvp_part, g_qkvp);
    cudaGetSymbolAddress(&opart, g_opart);
    cudaGetSymbolAddress(&biasqkv, g_biasqkv);

    float* qkvp = (float*)qkv;
    float* qkvpartp = (float*)qkvp_part;
    float* opartp = (float*)opart;

    cudaFuncSetAttribute(gemm_tc, cudaFuncAttributeMaxDynamicSharedMemorySize, GEMM_SMEM);
    cudaFuncSetAttribute(attn_kernel, cudaFuncAttributeMaxDynamicSharedMemorySize, ATTN_SMEM);

    // 1. pack inputs/weights (single fp16 plane each)
    pack_x<<<dim3(12, T_TOK), 256>>>(x, (__half*)xpk);
    tsp1<<<dim3(128, 90), dim3(32, 8)>>>(wq, (__half*)wbh, D_DIM, NH, NKC_QKV, 0);
    tsp1<<<dim3(16, 90), dim3(32, 8)>>>(wk, (__half*)wbh, D_DIM, KVH, NKC_QKV, NH);
    tsp1<<<dim3(16, 90), dim3(32, 8)>>>(wv, (__half*)wbh, D_DIM, KVH, NKC_QKV, NH + KVH);
    tsp1<<<dim3(92, 128), dim3(32, 8)>>>(wo, (__half*)wobh, NH, D_DIM, NKC_O, 0);
    concat_bias<<<(QKV_COLS + 255) / 256, 256>>>(bq, bk, bv, (float*)biasqkv);

    // 2. QKV projection: split-K=2 in one launch (z), then fused combine+rope
    gemm_tc<<<dim3(QKV_COLS / 128, T_TOK / 128, 2), 256, GEMM_SMEM>>>(
        (const __half*)xpk, (const __half*)wbh, qkvpartp,
        NKC_QKV, NKC_QKV / 2, QKV_COLS, QKV_COLS, (size_t)T_TOK * QKV_COLS);
    combine_qkv_rope<<<T_TOK, 256>>>(qkvpartp, (const float*)biasqkv, positions, qkvp);

    // 3. attention (writes packed fp16 ctx)
    attn_kernel<<<dim3(S_LEN / 4, 8, B_BATCH), 160, ATTN_SMEM>>>(
        qkvp, sinks, (__half*)cpk);

    // 4. output projection: split-K=2 in one launch (z), then combine (+bias)
    gemm_tc<<<dim3(OPAD / 128, T_TOK / 128, 2), 256, GEMM_SMEM>>>(
        (const __half*)cpk, (const __half*)wobh, opartp,
        NKC_O, NKC_O / 2, OPAD, OPAD, (size_t)T_TOK * OPAD);
    combine_o<<<T_TOK, 256>>>(opartp, bo, out);
}